// round 6
// baseline (speedup 1.0000x reference)
#include <cuda_runtime.h>
#include <cstdint>

#define NTOK 4096
#define BATCH 4
#define CIN 256
#define DI 128
#define DV 256
#define OUTC 256

typedef unsigned long long u64;
typedef uint32_t u32;

// ---------------- packed f32x2 helpers ----------------
__device__ __forceinline__ void ffma2(u64& d, u64 a, u64 b) {
    asm("fma.rn.f32x2 %0, %1, %2, %0;" : "+l"(d) : "l"(a), "l"(b));
}
__device__ __forceinline__ u64 pack2(float x, float y) {
    u64 r; asm("mov.b64 %0, {%1, %2};" : "=l"(r) : "f"(x), "f"(y)); return r;
}
__device__ __forceinline__ float2 unpack2(u64 a) {
    float2 f; asm("mov.b64 {%0, %1}, %2;" : "=f"(f.x), "=f"(f.y) : "l"(a)); return f;
}

// ---------------- tf32 mma (raw fp32 bits: HW reads bits[31:13]) ----------------
__device__ __forceinline__ void mma8(float4& d, u32 a0, u32 a1, u32 a2, u32 a3,
                                     u32 b0, u32 b1) {
    asm volatile(
        "mma.sync.aligned.m16n8k8.row.col.f32.tf32.tf32.f32 "
        "{%0,%1,%2,%3}, {%4,%5,%6,%7}, {%8,%9}, {%0,%1,%2,%3};"
        : "+f"(d.x), "+f"(d.y), "+f"(d.z), "+f"(d.w)
        : "r"(a0), "r"(a1), "r"(a2), "r"(a3), "r"(b0), "r"(b1));
}

// ---------------- cp.async helpers ----------------
__device__ __forceinline__ u32 smaddr(const void* p) {
    return (u32)__cvta_generic_to_shared(p);
}
__device__ __forceinline__ void cp16(u32 dst, const void* src) {
    asm volatile("cp.async.cg.shared.global [%0], [%1], 16;" :: "r"(dst), "l"(src));
}
#define CP_COMMIT() asm volatile("cp.async.commit_group;")
#define CP_WAIT1()  asm volatile("cp.async.wait_group 1;")
#define CP_WAIT0()  asm volatile("cp.async.wait_group 0;")

// ---------------- scratch ----------------
__device__ float g_Q[BATCH * NTOK * DI];     // [b][n][c], pre-scaled by 128^-0.5
__device__ float g_K[BATCH * NTOK * DI];     // [b][m][c]
__device__ float g_V[BATCH * NTOK * DV];     // [b][m][0:128]=v2, [128:256]=v1
__device__ float g_att[BATCH * NTOK * DV];   // [b][n][c]
__device__ float g_csum[BATCH * DV];

__global__ void zero_csum_kernel() { g_csum[threadIdx.x] = 0.0f; }

__global__ void colsum_kernel() {
    const int b = blockIdx.y;
    const int chunk = blockIdx.x;
    const int vc = threadIdx.x;
    const float* base = g_V + ((size_t)b * NTOK + (size_t)chunk * 64) * DV + vc;
    float s = 0.0f;
#pragma unroll 8
    for (int r = 0; r < 64; ++r) s += base[(size_t)r * DV];
    atomicAdd(&g_csum[b * DV + vc], s);
}

// Fused QKV projections (fp32, f32x2 inner loop). z selects variant.
__global__ __launch_bounds__(256)
void qkv_proj_kernel(const float* __restrict__ x1, const float* __restrict__ x2,
                     const float* __restrict__ Wq, const float* __restrict__ bq,
                     const float* __restrict__ sq, const float* __restrict__ tq,
                     const float* __restrict__ Wk, const float* __restrict__ bk,
                     const float* __restrict__ sk, const float* __restrict__ tk,
                     const float* __restrict__ Wv, const float* __restrict__ bv,
                     const float* __restrict__ sv, const float* __restrict__ tv,
                     float* __restrict__ pQ, float* __restrict__ pK, float* __restrict__ pV) {
    __shared__ float Xs[32 * 68];
    __shared__ float Ws[128 * 33];
    const int z = blockIdx.z;
    const float* x; const float* W; const float* bias; const float* sc; const float* tr;
    float* outp; int ostride; float prescale;
    if (z == 0)      { x = x1; W = Wq; bias = bq; sc = sq; tr = tq; outp = pQ;      ostride = DI; prescale = 0.08838834764831845f; }
    else if (z == 1) { x = x2; W = Wk; bias = bk; sc = sk; tr = tk; outp = pK;      ostride = DI; prescale = 1.0f; }
    else if (z == 2) { x = x2; W = Wv; bias = bv; sc = sv; tr = tv; outp = pV;      ostride = DV; prescale = 1.0f; }
    else             { x = x1; W = Wv; bias = bv; sc = sv; tr = tv; outp = pV + DI; ostride = DV; prescale = 1.0f; }

    const int b = blockIdx.y;
    const int nbase = blockIdx.x * 64;
    const int tid = threadIdx.x;
    const int tx = tid & 15, ty = tid >> 4;
    const float* xg = x + (size_t)b * CIN * NTOK;

    u64 accp[2][8];
#pragma unroll
    for (int i = 0; i < 2; ++i)
#pragma unroll
        for (int jj = 0; jj < 8; ++jj) accp[i][jj] = 0ull;

    for (int c0 = 0; c0 < CIN; c0 += 32) {
        __syncthreads();
#pragma unroll
        for (int it = 0; it < 2; ++it) {
            int idx = tid + it * 256;
            int r = idx >> 4, c4 = idx & 15;
            *(float4*)&Xs[r * 68 + c4 * 4] =
                *(const float4*)&xg[(size_t)(c0 + r) * NTOK + nbase + c4 * 4];
        }
#pragma unroll
        for (int it = 0; it < 16; ++it) {
            int idx = tid + it * 256;
            int r = idx >> 5, c = idx & 31;
            Ws[r * 33 + c] = W[(size_t)r * CIN + c0 + c];
        }
        __syncthreads();
#pragma unroll 4
        for (int c = 0; c < 32; ++c) {
            ulonglong2 xp = *(const ulonglong2*)&Xs[c * 68 + 4 * ty];
#pragma unroll
            for (int jj = 0; jj < 8; ++jj) {
                float w = Ws[(tx + 16 * jj) * 33 + c];
                u64 w2 = pack2(w, w);
                ffma2(accp[0][jj], xp.x, w2);
                ffma2(accp[1][jj], xp.y, w2);
            }
        }
    }
#pragma unroll
    for (int jj = 0; jj < 8; ++jj) {
        int o = tx + 16 * jj;
        float bb = bias[o], ss = sc[o], tt = tr[o];
#pragma unroll
        for (int i2 = 0; i2 < 2; ++i2) {
            float2 a = unpack2(accp[i2][jj]);
            float v0 = (a.x + bb) * ss + tt; v0 = v0 > 0.0f ? v0 : 0.0f;
            float v1 = (a.y + bb) * ss + tt; v1 = v1 > 0.0f ? v1 : 0.0f;
            size_t row = (size_t)b * NTOK + nbase + 4 * ty + 2 * i2;
            outp[row * ostride + o] = v0 * prescale;
            outp[(row + 1) * ostride + o] = v1 * prescale;
        }
    }
}

// ============================================================================
// Flash attention w/ complement, tf32 mma on RAW fp32 bits, cp.async pipelined.
// att[b][n][vc] = csum[b][vc] - softmax(QK^T)[n][m] · V[m][vc]
// BR=BC=64, D=128, DV=256. 512 threads = 16 warps: 4(row) x 4(col).
//   warp wr owns S-rows [16wr,16wr+16); warp wc owns S-cols [16wc,16wc+16)
//   in QK phase and V-cols [64wc,64wc+64) in PV phase.
// Single-buffer pipeline: K(mb+1) loads during softmax+PV(mb);
// V(mb+1) loads during S(mb+1)'s preceding phase.
// ============================================================================
__global__ __launch_bounds__(512, 1)
void attn_kernel(const float* __restrict__ Q, const float* __restrict__ K,
                 const float* __restrict__ V, const float* __restrict__ csum,
                 float* __restrict__ att) {
    extern __shared__ u32 sm[];
    u32* Qs = sm;                       // 64 x 132
    u32* Ks = Qs + 64 * 132;            // 64 x 132
    u32* Vs = Ks + 64 * 132;            // 64 x 260
    u32* Ps = Vs + 64 * 260;            // 64 x 68  (probs, raw fp32 bits, [row][m])
    float* red = (float*)(Ps + 64 * 68);  // [0:256) max partials, [256:512) sums

    const int b = blockIdx.y;
    const int nbase = blockIdx.x * 64;
    const int tid = threadIdx.x;
    const int wid = tid >> 5, lane = tid & 31;
    const int wr = wid >> 2, wc = wid & 3;
    const int gq = lane >> 2, qd = lane & 3;
    const int row0 = 16 * wr + gq;

    // per-thread cp.async slots (512 threads)
    const int rK = tid >> 5, cK = (tid & 31) * 4;        // K/Q: 4 iters of (rK+16it)
    const int rV = tid >> 6, cV = (tid & 63) * 4;        // V: 8 iters of (rV+8it)
    const float* Qg = Q + ((size_t)b * NTOK + nbase) * DI;
    const float* Kg0 = K + (size_t)b * NTOK * DI;
    const float* Vg0 = V + (size_t)b * NTOK * DV;

    // ---- prologue: group A = Q + K(0); group B = V(0) ----
#pragma unroll
    for (int it = 0; it < 4; ++it) {
        int r = rK + 16 * it;
        cp16(smaddr(&Qs[r * 132 + cK]), Qg + (size_t)r * DI + cK);
        cp16(smaddr(&Ks[r * 132 + cK]), Kg0 + (size_t)r * DI + cK);
    }
    CP_COMMIT();
#pragma unroll
    for (int it = 0; it < 8; ++it) {
        int r = rV + 8 * it;
        cp16(smaddr(&Vs[r * 260 + cV]), Vg0 + (size_t)r * DV + cV);
    }
    CP_COMMIT();

    float M0 = -1e30f, M1 = -1e30f, L0 = 0.0f, L1 = 0.0f;
    float4 acc[8];                       // O accum: tile t -> cols 64*wc+8t+2qd(+1)
#pragma unroll
    for (int t = 0; t < 8; ++t) acc[t] = make_float4(0.f, 0.f, 0.f, 0.f);

    for (int mb = 0; mb < NTOK; mb += 64) {
        const bool more = (mb + 64) < NTOK;
        // K(mb) (and Q on first iter) ready; V(mb) may still be in flight
        CP_WAIT1();
        __syncthreads();

        // ---- S = Q K^T (warp computes 16x16) ----
        float4 S[2];
        S[0] = make_float4(0.f, 0.f, 0.f, 0.f);
        S[1] = make_float4(0.f, 0.f, 0.f, 0.f);
#pragma unroll
        for (int kk = 0; kk < 16; ++kk) {
            int k = kk * 8 + qd;
            u32 a0 = Qs[row0 * 132 + k];
            u32 a1 = Qs[(row0 + 8) * 132 + k];
            u32 a2 = Qs[row0 * 132 + k + 4];
            u32 a3 = Qs[(row0 + 8) * 132 + k + 4];
#pragma unroll
            for (int t = 0; t < 2; ++t) {
                int n = 16 * wc + 8 * t + gq;
                u32 b0 = Ks[n * 132 + k];
                u32 b1 = Ks[n * 132 + k + 4];
                mma8(S[t], a0, a1, a2, a3, b0, b1);
            }
        }
        __syncthreads();          // all warps done reading Ks

        // ---- prefetch K(mb+64) into Ks (overlaps softmax + PV) ----
        if (more) {
            const float* Kg = Kg0 + (size_t)(mb + 64) * DI;
#pragma unroll
            for (int it = 0; it < 4; ++it) {
                int r = rK + 16 * it;
                cp16(smaddr(&Ks[r * 132 + cK]), Kg + (size_t)r * DI + cK);
            }
            CP_COMMIT();
        }

        // ---- row max (quad shuffle -> cross-warp via smem, 4 col-warp partials) ----
        float mx0 = fmaxf(fmaxf(S[0].x, S[0].y), fmaxf(S[1].x, S[1].y));
        float mx1 = fmaxf(fmaxf(S[0].z, S[0].w), fmaxf(S[1].z, S[1].w));
        mx0 = fmaxf(mx0, __shfl_xor_sync(0xffffffffu, mx0, 1));
        mx0 = fmaxf(mx0, __shfl_xor_sync(0xffffffffu, mx0, 2));
        mx1 = fmaxf(mx1, __shfl_xor_sync(0xffffffffu, mx1, 1));
        mx1 = fmaxf(mx1, __shfl_xor_sync(0xffffffffu, mx1, 2));
        if (qd == 0) {
            red[wc * 64 + row0] = mx0;
            red[wc * 64 + row0 + 8] = mx1;
        }
        __syncthreads();
        float newM0 = fmaxf(fmaxf(red[row0], red[64 + row0]),
                            fmaxf(red[128 + row0], red[192 + row0]));
        float newM1 = fmaxf(fmaxf(red[row0 + 8], red[64 + row0 + 8]),
                            fmaxf(red[128 + row0 + 8], red[192 + row0 + 8]));
        newM0 = fmaxf(M0, newM0);
        newM1 = fmaxf(M1, newM1);

        // ---- exp + partial sums + store P (raw fp32 bits) ----
        float s0 = 0.0f, s1 = 0.0f;
#pragma unroll
        for (int t = 0; t < 2; ++t) {
            S[t].x = __expf(S[t].x - newM0);
            S[t].y = __expf(S[t].y - newM0);
            S[t].z = __expf(S[t].z - newM1);
            S[t].w = __expf(S[t].w - newM1);
            s0 += S[t].x + S[t].y;
            s1 += S[t].z + S[t].w;
            int col = 16 * wc + 8 * t + 2 * qd;
            *(uint2*)&Ps[row0 * 68 + col] =
                make_uint2(__float_as_uint(S[t].x), __float_as_uint(S[t].y));
            *(uint2*)&Ps[(row0 + 8) * 68 + col] =
                make_uint2(__float_as_uint(S[t].z), __float_as_uint(S[t].w));
        }
        s0 += __shfl_xor_sync(0xffffffffu, s0, 1);
        s0 += __shfl_xor_sync(0xffffffffu, s0, 2);
        s1 += __shfl_xor_sync(0xffffffffu, s1, 1);
        s1 += __shfl_xor_sync(0xffffffffu, s1, 2);
        if (qd == 0) {
            red[256 + wc * 64 + row0] = s0;
            red[256 + wc * 64 + row0 + 8] = s1;
        }
        // V(mb) must be resident for PV; K(mb+64) group may stay in flight
        if (more) CP_WAIT1(); else CP_WAIT0();
        __syncthreads();   // orders P stores + red sums + V arrival

        float corr0 = __expf(M0 - newM0);
        float corr1 = __expf(M1 - newM1);
        L0 = L0 * corr0 + (red[256 + row0] + red[320 + row0]) +
             (red[384 + row0] + red[448 + row0]);
        L1 = L1 * corr1 + (red[256 + row0 + 8] + red[320 + row0 + 8]) +
             (red[384 + row0 + 8] + red[448 + row0 + 8]);
        M0 = newM0; M1 = newM1;
#pragma unroll
        for (int t = 0; t < 8; ++t) {
            acc[t].x *= corr0; acc[t].y *= corr0;
            acc[t].z *= corr1; acc[t].w *= corr1;
        }

        // ---- O += P V (warp computes 16x64 at vc base 64*wc) ----
#pragma unroll
        for (int kk = 0; kk < 8; ++kk) {
            int k = kk * 8 + qd;
            u32 a0 = Ps[row0 * 68 + k];
            u32 a1 = Ps[(row0 + 8) * 68 + k];
            u32 a2 = Ps[row0 * 68 + k + 4];
            u32 a3 = Ps[(row0 + 8) * 68 + k + 4];
            int m0 = kk * 8 + qd;
#pragma unroll
            for (int t = 0; t < 8; ++t) {
                int vc = 64 * wc + 8 * t + gq;
                u32 b0 = Vs[m0 * 260 + vc];
                u32 b1 = Vs[(m0 + 4) * 260 + vc];
                mma8(acc[t], a0, a1, a2, a3, b0, b1);
            }
        }
        __syncthreads();          // all warps done reading Vs (and Ps)

        // ---- prefetch V(mb+64) into Vs (overlaps next S) ----
        if (more) {
            const float* Vg = Vg0 + (size_t)(mb + 64) * DV;
#pragma unroll
            for (int it = 0; it < 8; ++it) {
                int r = rV + 8 * it;
                cp16(smaddr(&Vs[r * 260 + cV]), Vg + (size_t)r * DV + cV);
            }
            CP_COMMIT();
        }
    }

    // ---- epilogue: att = csum - acc / L ----
    const float* cs = csum + b * DV;
    float* og = att + ((size_t)b * NTOK + nbase) * DV;
    float inv0 = 1.0f / L0, inv1 = 1.0f / L1;
#pragma unroll
    for (int t = 0; t < 8; ++t) {
        int col = 64 * wc + 8 * t + 2 * qd;
        float2 c0 = *(const float2*)&cs[col];
        float2 r0, r1;
        r0.x = c0.x - acc[t].x * inv0;
        r0.y = c0.y - acc[t].y * inv0;
        r1.x = c0.x - acc[t].z * inv1;
        r1.y = c0.y - acc[t].w * inv1;
        *(float2*)&og[(size_t)row0 * DV + col] = r0;
        *(float2*)&og[(size_t)(row0 + 8) * DV + col] = r1;
    }
}

// out[b][o][n] = relu((sum_c Wp[o][c]*att[b][n][c] + bias[o])*sc[o] + tr[o])
__global__ __launch_bounds__(256)
void projf_kernel(const float* __restrict__ A, const float* __restrict__ W,
                  const float* __restrict__ bias, const float* __restrict__ sc,
                  const float* __restrict__ tr, float* __restrict__ out) {
    __shared__ float As[32 * 68];
    __shared__ float Ws[64 * 33];
    const int b = blockIdx.z;
    const int obase = blockIdx.y * 64;
    const int nbase = blockIdx.x * 64;
    const int tid = threadIdx.x;
    const int tx = tid & 15, ty = tid >> 4;
    const float* Ag = A + (size_t)b * NTOK * DV;

    u64 accp[4][2];
#pragma unroll
    for (int i = 0; i < 4; ++i) { accp[i][0] = 0ull; accp[i][1] = 0ull; }

    for (int c0 = 0; c0 < DV; c0 += 32) {
        __syncthreads();
#pragma unroll
        for (int it = 0; it < 2; ++it) {
            int idx = tid + it * 256;
            int n = idx >> 3, c4 = idx & 7;
            float4 v = *(const float4*)&Ag[(size_t)(nbase + n) * DV + c0 + c4 * 4];
            As[(c4 * 4 + 0) * 68 + n] = v.x;
            As[(c4 * 4 + 1) * 68 + n] = v.y;
            As[(c4 * 4 + 2) * 68 + n] = v.z;
            As[(c4 * 4 + 3) * 68 + n] = v.w;
        }
#pragma unroll
        for (int it = 0; it < 8; ++it) {
            int idx = tid + it * 256;
            int r = idx >> 5, c = idx & 31;
            Ws[r * 33 + c] = W[(size_t)(obase + r) * DV + c0 + c];
        }
        __syncthreads();
#pragma unroll 4
        for (int c = 0; c < 32; ++c) {
            ulonglong2 ap = *(const ulonglong2*)&As[c * 68 + 4 * tx];
#pragma unroll
            for (int i = 0; i < 4; ++i) {
                float w = Ws[(4 * ty + i) * 33 + c];
                u64 w2 = pack2(w, w);
                ffma2(accp[i][0], w2, ap.x);
                ffma2(accp[i][1], w2, ap.y);
            }
        }
    }
#pragma unroll
    for (int i = 0; i < 4; ++i) {
        int o = obase + 4 * ty + i;
        float bb = bias[o], ss = sc[o], tt = tr[o];
        float2 a0 = unpack2(accp[i][0]);
        float2 a1 = unpack2(accp[i][1]);
        float4 r;
        r.x = (a0.x + bb) * ss + tt; r.x = r.x > 0.f ? r.x : 0.f;
        r.y = (a0.y + bb) * ss + tt; r.y = r.y > 0.f ? r.y : 0.f;
        r.z = (a1.x + bb) * ss + tt; r.z = r.z > 0.f ? r.z : 0.f;
        r.w = (a1.y + bb) * ss + tt; r.w = r.w > 0.f ? r.w : 0.f;
        *(float4*)&out[((size_t)b * OUTC + o) * NTOK + nbase + 4 * tx] = r;
    }
}

extern "C" void kernel_launch(void* const* d_in, const int* in_sizes, int n_in,
                              void* d_out, int out_size) {
    const float* x1 = (const float*)d_in[0];
    const float* x2 = (const float*)d_in[1];
    const float* Wq = (const float*)d_in[2];
    const float* bq = (const float*)d_in[3];
    const float* sq = (const float*)d_in[4];
    const float* tq = (const float*)d_in[5];
    const float* Wk = (const float*)d_in[6];
    const float* bk = (const float*)d_in[7];
    const float* sk = (const float*)d_in[8];
    const float* tk = (const float*)d_in[9];
    const float* Wv = (const float*)d_in[10];
    const float* bv = (const float*)d_in[11];
    const float* sv = (const float*)d_in[12];
    const float* tv = (const float*)d_in[13];
    const float* Wp = (const float*)d_in[14];
    const float* bp = (const float*)d_in[15];
    const float* sp = (const float*)d_in[16];
    const float* tp = (const float*)d_in[17];
    float* out = (float*)d_out;

    float *pQ, *pK, *pV, *pAtt, *pCs;
    cudaGetSymbolAddress((void**)&pQ, g_Q);
    cudaGetSymbolAddress((void**)&pK, g_K);
    cudaGetSymbolAddress((void**)&pV, g_V);
    cudaGetSymbolAddress((void**)&pAtt, g_att);
    cudaGetSymbolAddress((void**)&pCs, g_csum);

    // Qs+Ks (64x132 each) + Vs (64x260) + Ps (64x68) + red (512 floats)
    const int SMEM_ATTN = (64 * 132 * 2 + 64 * 260 + 64 * 68 + 512) * 4;  // 153600 B
    cudaFuncSetAttribute(attn_kernel, cudaFuncAttributeMaxDynamicSharedMemorySize, SMEM_ATTN);

    qkv_proj_kernel<<<dim3(NTOK / 64, BATCH, 4), 256>>>(
        x1, x2, Wq, bq, sq, tq, Wk, bk, sk, tk, Wv, bv, sv, tv, pQ, pK, pV);
    zero_csum_kernel<<<1, BATCH * DV>>>();
    colsum_kernel<<<dim3(NTOK / 64, BATCH), 256>>>();
    attn_kernel<<<dim3(NTOK / 64, BATCH), 512, SMEM_ATTN>>>(pQ, pK, pV, pCs, pAtt);
    projf_kernel<<<dim3(NTOK / 64, OUTC / 64, BATCH), 256>>>(pAtt, Wp, bp, sp, tp, out);
}

// round 7
// speedup vs baseline: 2.0539x; 2.0539x over previous
#include <cuda_runtime.h>
#include <cuda_bf16.h>
#include <cstdint>

#define NTOK 4096
#define BATCH 4
#define CIN 256
#define DI 128
#define DV 256
#define OUTC 256

typedef unsigned long long u64;
typedef uint32_t u32;

// ---------------- packed f32x2 helpers (proj kernels) ----------------
__device__ __forceinline__ void ffma2(u64& d, u64 a, u64 b) {
    asm("fma.rn.f32x2 %0, %1, %2, %0;" : "+l"(d) : "l"(a), "l"(b));
}
__device__ __forceinline__ u64 pack2(float x, float y) {
    u64 r; asm("mov.b64 %0, {%1, %2};" : "=l"(r) : "f"(x), "f"(y)); return r;
}
__device__ __forceinline__ float2 unpack2(u64 a) {
    float2 f; asm("mov.b64 {%0, %1}, %2;" : "=f"(f.x), "=f"(f.y) : "l"(a)); return f;
}

// ---------------- bf16 mma + ldmatrix ----------------
__device__ __forceinline__ void mmabf(float4& d, u32 a0, u32 a1, u32 a2, u32 a3,
                                      u32 b0, u32 b1) {
    asm volatile(
        "mma.sync.aligned.m16n8k16.row.col.f32.bf16.bf16.f32 "
        "{%0,%1,%2,%3}, {%4,%5,%6,%7}, {%8,%9}, {%0,%1,%2,%3};"
        : "+f"(d.x), "+f"(d.y), "+f"(d.z), "+f"(d.w)
        : "r"(a0), "r"(a1), "r"(a2), "r"(a3), "r"(b0), "r"(b1));
}
__device__ __forceinline__ void ldmx4(u32& r0, u32& r1, u32& r2, u32& r3, u32 a) {
    asm volatile("ldmatrix.sync.aligned.m8n8.x4.shared.b16 {%0,%1,%2,%3}, [%4];"
                 : "=r"(r0), "=r"(r1), "=r"(r2), "=r"(r3) : "r"(a));
}
__device__ __forceinline__ void ldmx4t(u32& r0, u32& r1, u32& r2, u32& r3, u32 a) {
    asm volatile("ldmatrix.sync.aligned.m8n8.x4.trans.shared.b16 {%0,%1,%2,%3}, [%4];"
                 : "=r"(r0), "=r"(r1), "=r"(r2), "=r"(r3) : "r"(a));
}
__device__ __forceinline__ u32 pkbf(float lo, float hi) {   // lo -> lower half
    u32 r; asm("cvt.rn.bf16x2.f32 %0, %1, %2;" : "=r"(r) : "f"(hi), "f"(lo)); return r;
}

// ---------------- cp.async helpers ----------------
__device__ __forceinline__ u32 smaddr(const void* p) {
    return (u32)__cvta_generic_to_shared(p);
}
__device__ __forceinline__ void cp16(u32 dst, const void* src) {
    asm volatile("cp.async.cg.shared.global [%0], [%1], 16;" :: "r"(dst), "l"(src));
}
#define CP_COMMIT() asm volatile("cp.async.commit_group;")
#define CP_WAIT1()  asm volatile("cp.async.wait_group 1;")
#define CP_WAIT0()  asm volatile("cp.async.wait_group 0;")

// ---------------- scratch ----------------
__device__ __nv_bfloat16 g_Qh[BATCH * NTOK * DI];   // [b][n][c] bf16, pre-scaled
__device__ __nv_bfloat16 g_Kh[BATCH * NTOK * DI];
__device__ __nv_bfloat16 g_Vh[BATCH * NTOK * DV];   // [0:128)=v2, [128:256)=v1
__device__ float g_Vf[BATCH * NTOK * DV];           // fp32 copy for exact colsum
__device__ float g_att[BATCH * NTOK * DV];
__device__ float g_csum[BATCH * DV];

__global__ void zero_csum_kernel() { g_csum[threadIdx.x] = 0.0f; }

__global__ void colsum_kernel() {
    const int b = blockIdx.y;
    const int chunk = blockIdx.x;
    const int vc = threadIdx.x;
    const float* base = g_Vf + ((size_t)b * NTOK + (size_t)chunk * 64) * DV + vc;
    float s = 0.0f;
#pragma unroll 8
    for (int r = 0; r < 64; ++r) s += base[(size_t)r * DV];
    atomicAdd(&g_csum[b * DV + vc], s);
}

// Fused QKV projections (fp32 math, bf16 outputs). z selects variant.
__global__ __launch_bounds__(256)
void qkv_proj_kernel(const float* __restrict__ x1, const float* __restrict__ x2,
                     const float* __restrict__ Wq, const float* __restrict__ bq,
                     const float* __restrict__ sq, const float* __restrict__ tq,
                     const float* __restrict__ Wk, const float* __restrict__ bk,
                     const float* __restrict__ sk, const float* __restrict__ tk,
                     const float* __restrict__ Wv, const float* __restrict__ bv,
                     const float* __restrict__ sv, const float* __restrict__ tv,
                     __nv_bfloat16* __restrict__ pQ, __nv_bfloat16* __restrict__ pK,
                     __nv_bfloat16* __restrict__ pVh, float* __restrict__ pVf) {
    __shared__ float Xs[32 * 68];
    __shared__ float Ws[128 * 33];
    const int z = blockIdx.z;
    const float* x; const float* W; const float* bias; const float* sc; const float* tr;
    float prescale;
    if (z == 0)      { x = x1; W = Wq; bias = bq; sc = sq; tr = tq; prescale = 0.08838834764831845f; }
    else if (z == 1) { x = x2; W = Wk; bias = bk; sc = sk; tr = tk; prescale = 1.0f; }
    else if (z == 2) { x = x2; W = Wv; bias = bv; sc = sv; tr = tv; prescale = 1.0f; }
    else             { x = x1; W = Wv; bias = bv; sc = sv; tr = tv; prescale = 1.0f; }

    const int b = blockIdx.y;
    const int nbase = blockIdx.x * 64;
    const int tid = threadIdx.x;
    const int tx = tid & 15, ty = tid >> 4;
    const float* xg = x + (size_t)b * CIN * NTOK;

    u64 accp[2][8];
#pragma unroll
    for (int i = 0; i < 2; ++i)
#pragma unroll
        for (int jj = 0; jj < 8; ++jj) accp[i][jj] = 0ull;

    for (int c0 = 0; c0 < CIN; c0 += 32) {
        __syncthreads();
#pragma unroll
        for (int it = 0; it < 2; ++it) {
            int idx = tid + it * 256;
            int r = idx >> 4, c4 = idx & 15;
            *(float4*)&Xs[r * 68 + c4 * 4] =
                *(const float4*)&xg[(size_t)(c0 + r) * NTOK + nbase + c4 * 4];
        }
#pragma unroll
        for (int it = 0; it < 16; ++it) {
            int idx = tid + it * 256;
            int r = idx >> 5, c = idx & 31;
            Ws[r * 33 + c] = W[(size_t)r * CIN + c0 + c];
        }
        __syncthreads();
#pragma unroll 4
        for (int c = 0; c < 32; ++c) {
            ulonglong2 xp = *(const ulonglong2*)&Xs[c * 68 + 4 * ty];
#pragma unroll
            for (int jj = 0; jj < 8; ++jj) {
                float w = Ws[(tx + 16 * jj) * 33 + c];
                u64 w2 = pack2(w, w);
                ffma2(accp[0][jj], xp.x, w2);
                ffma2(accp[1][jj], xp.y, w2);
            }
        }
    }
#pragma unroll
    for (int jj = 0; jj < 8; ++jj) {
        int o = tx + 16 * jj;
        float bb = bias[o], ss = sc[o], tt = tr[o];
#pragma unroll
        for (int i2 = 0; i2 < 2; ++i2) {
            float2 a = unpack2(accp[i2][jj]);
            float v0 = (a.x + bb) * ss + tt; v0 = v0 > 0.0f ? v0 : 0.0f; v0 *= prescale;
            float v1 = (a.y + bb) * ss + tt; v1 = v1 > 0.0f ? v1 : 0.0f; v1 *= prescale;
            size_t row = (size_t)b * NTOK + nbase + 4 * ty + 2 * i2;
            if (z == 0) {
                pQ[row * DI + o] = __float2bfloat16(v0);
                pQ[(row + 1) * DI + o] = __float2bfloat16(v1);
            } else if (z == 1) {
                pK[row * DI + o] = __float2bfloat16(v0);
                pK[(row + 1) * DI + o] = __float2bfloat16(v1);
            } else {
                int oc = o + (z == 3 ? 128 : 0);
                pVf[row * DV + oc] = v0;
                pVf[(row + 1) * DV + oc] = v1;
                pVh[row * DV + oc] = __float2bfloat16(v0);
                pVh[(row + 1) * DV + oc] = __float2bfloat16(v1);
            }
        }
    }
}

// ============================================================================
// bf16 flash attention with complement. BR=BC=64, D=128, DV=256.
// 256 threads = 8 warps. S phase: 4(row wr)x2(col wc); PV phase: 2(row wp)x4(col wq).
// K double-buffered (cp.async), V single-buffered. ldmatrix fragment loads.
// Smem strides (halves): Q/K 136, V 264, P 72 — all conflict-free for ldmatrix.
// ============================================================================
#define QK_S 136
#define V_S  264
#define P_S  72
#define OFF_K 8704          // halves: Qh = [0,8704), Kh = [8704, 26112) (2 bufs)
#define OFF_V 26112         // Vh = [26112, 43008)
#define OFF_P 43008         // Ph = [43008, 47616)
#define OFF_RED 47616       // floats after this

__global__ __launch_bounds__(256, 2)
void attn_kernel(const __nv_bfloat16* __restrict__ Q, const __nv_bfloat16* __restrict__ K,
                 const __nv_bfloat16* __restrict__ V, const float* __restrict__ csum,
                 float* __restrict__ att) {
    extern __shared__ uint16_t smh[];
    float* red = (float*)(smh + OFF_RED);   // [0:128) mx, [128:256) sums, [256:320) corr, [320:384) L

    const int b = blockIdx.y;
    const int nbase = blockIdx.x * 64;
    const int tid = threadIdx.x;
    const int wid = tid >> 5, lane = tid & 31;
    const int wr = wid >> 1, wc = wid & 1;      // S phase 4x2
    const int wp = wid >> 2, wq = wid & 3;      // PV phase 2x4
    const int gq = lane >> 2, qd = lane & 3;
    const int row0 = 16 * wr + gq;              // softmax-owned rows (row0, row0+8)

    // cp.async slots
    const int rK = tid >> 4, cK = (tid & 15) * 8;    // Q/K rows: 4 iters of rK+16it
    const int rV = tid >> 5, cV = (tid & 31) * 8;    // V rows: 8 iters of rV+8it
    const __nv_bfloat16* Qg = Q + ((size_t)b * NTOK + nbase) * DI;
    const __nv_bfloat16* Kg0 = K + (size_t)b * NTOK * DI;
    const __nv_bfloat16* Vg0 = V + (size_t)b * NTOK * DV;
    const u32 smbase = smaddr(smh);

    // ---- prologue: G0 = {Q, K(0)}, G1 = {V(0)} ----
#pragma unroll
    for (int it = 0; it < 4; ++it) {
        int r = rK + 16 * it;
        cp16(smbase + (r * QK_S + cK) * 2, Qg + (size_t)r * DI + cK);
        cp16(smbase + (OFF_K + r * QK_S + cK) * 2, Kg0 + (size_t)r * DI + cK);
    }
    CP_COMMIT();
#pragma unroll
    for (int it = 0; it < 8; ++it) {
        int r = rV + 8 * it;
        cp16(smbase + (OFF_V + r * V_S + cV) * 2, Vg0 + (size_t)r * DV + cV);
    }
    CP_COMMIT();

    // ldmatrix base addresses (bytes)
    const u32 aQ = smbase + ((16 * wr + (lane & 15)) * QK_S + (lane >> 4) * 8) * 2;
    const u32 aKoff = ((32 * wc + (lane & 7) + (lane >> 4) * 8) * QK_S +
                       ((lane >> 3) & 1) * 8) * 2;
    const u32 aP0 = smbase + (OFF_P + (32 * wp + (lane & 15)) * P_S + (lane >> 4) * 8) * 2;
    const u32 aP1 = aP0 + 16 * P_S * 2;
    const u32 aV = smbase + (OFF_V + ((lane & 7) + ((lane >> 3) & 1) * 8) * V_S +
                             64 * wq + (lane >> 4) * 8) * 2;

    float M0 = -1e30f, M1 = -1e30f, L0 = 0.0f, L1 = 0.0f;
    float4 acc[2][8];   // [rowfrag f: rows 32wp+16f+gq(+8)][ntile t: cols 64wq+8t+2qd]
#pragma unroll
    for (int f = 0; f < 2; ++f)
#pragma unroll
        for (int t = 0; t < 8; ++t) acc[f][t] = make_float4(0.f, 0.f, 0.f, 0.f);

    int par = 0;
    for (int mb = 0; mb < NTOK; mb += 64, par ^= 1) {
        const bool more = (mb + 64) < NTOK;
        CP_WAIT1();            // K(mb) (and Q) resident; V(mb) may be in flight
        __syncthreads();       // (1)

        // prefetch K(mb+1) into other buffer (overlaps S + softmax + PV)
        if (more) {
            const __nv_bfloat16* Kg = Kg0 + (size_t)(mb + 64) * DI;
            u32 kd = smbase + (OFF_K + (par ^ 1) * 8704) * 2;
#pragma unroll
            for (int it = 0; it < 4; ++it) {
                int r = rK + 16 * it;
                cp16(kd + (r * QK_S + cK) * 2, Kg + (size_t)r * DI + cK);
            }
            CP_COMMIT();
        }

        // ---- S = Q K^T (warp: 16 rows x 32 cols, 4 n-tiles) ----
        float4 S[4];
#pragma unroll
        for (int t = 0; t < 4; ++t) S[t] = make_float4(0.f, 0.f, 0.f, 0.f);
        const u32 aK = smbase + (OFF_K + par * 8704) * 2 + aKoff;
        const u32 aK2 = aK + 16 * QK_S * 2;
#pragma unroll
        for (int kk = 0; kk < 8; ++kk) {
            u32 a0, a1, a2, a3, b00, b01, b10, b11, b20, b21, b30, b31;
            ldmx4(a0, a1, a2, a3, aQ + kk * 32);
            ldmx4(b00, b01, b10, b11, aK + kk * 32);
            ldmx4(b20, b21, b30, b31, aK2 + kk * 32);
            mmabf(S[0], a0, a1, a2, a3, b00, b01);
            mmabf(S[1], a0, a1, a2, a3, b10, b11);
            mmabf(S[2], a0, a1, a2, a3, b20, b21);
            mmabf(S[3], a0, a1, a2, a3, b30, b31);
        }

        // ---- row max: quad shuffle -> cross-warp partials ----
        float mx0 = fmaxf(fmaxf(S[0].x, S[0].y), fmaxf(S[1].x, S[1].y));
        mx0 = fmaxf(mx0, fmaxf(fmaxf(S[2].x, S[2].y), fmaxf(S[3].x, S[3].y)));
        float mx1 = fmaxf(fmaxf(S[0].z, S[0].w), fmaxf(S[1].z, S[1].w));
        mx1 = fmaxf(mx1, fmaxf(fmaxf(S[2].z, S[2].w), fmaxf(S[3].z, S[3].w)));
        mx0 = fmaxf(mx0, __shfl_xor_sync(0xffffffffu, mx0, 1));
        mx0 = fmaxf(mx0, __shfl_xor_sync(0xffffffffu, mx0, 2));
        mx1 = fmaxf(mx1, __shfl_xor_sync(0xffffffffu, mx1, 1));
        mx1 = fmaxf(mx1, __shfl_xor_sync(0xffffffffu, mx1, 2));
        if (qd == 0) {
            red[wc * 64 + row0] = mx0;
            red[wc * 64 + row0 + 8] = mx1;
        }
        __syncthreads();       // (2)
        float newM0 = fmaxf(M0, fmaxf(red[row0], red[64 + row0]));
        float newM1 = fmaxf(M1, fmaxf(red[row0 + 8], red[64 + row0 + 8]));
        float corr0 = __expf(M0 - newM0);
        float corr1 = __expf(M1 - newM1);
        if (wc == 0 && qd == 0) {
            red[256 + row0] = corr0;
            red[256 + row0 + 8] = corr1;
        }

        // ---- exp + partial sums + P store (bf16) ----
        float s0 = 0.0f, s1 = 0.0f;
#pragma unroll
        for (int t = 0; t < 4; ++t) {
            S[t].x = __expf(S[t].x - newM0);
            S[t].y = __expf(S[t].y - newM0);
            S[t].z = __expf(S[t].z - newM1);
            S[t].w = __expf(S[t].w - newM1);
            s0 += S[t].x + S[t].y;
            s1 += S[t].z + S[t].w;
            int col = 32 * wc + 8 * t + 2 * qd;
            *(u32*)(smh + OFF_P + row0 * P_S + col) = pkbf(S[t].x, S[t].y);
            *(u32*)(smh + OFF_P + (row0 + 8) * P_S + col) = pkbf(S[t].z, S[t].w);
        }
        s0 += __shfl_xor_sync(0xffffffffu, s0, 1);
        s0 += __shfl_xor_sync(0xffffffffu, s0, 2);
        s1 += __shfl_xor_sync(0xffffffffu, s1, 1);
        s1 += __shfl_xor_sync(0xffffffffu, s1, 2);
        if (qd == 0) {
            red[128 + wc * 64 + row0] = s0;
            red[128 + wc * 64 + row0 + 8] = s1;
        }
        if (more) CP_WAIT1(); else CP_WAIT0();   // V(mb) resident; K(mb+1) may pend
        __syncthreads();       // (3) P + partials + corr visible, V ready

        L0 = L0 * corr0 + red[128 + row0] + red[192 + row0];
        L1 = L1 * corr1 + red[128 + row0 + 8] + red[192 + row0 + 8];
        M0 = newM0; M1 = newM1;

        // ---- PV: scale acc by per-row corr (PV rows != softmax rows) ----
        float cA0 = red[256 + 32 * wp + gq];
        float cB0 = red[256 + 32 * wp + 8 + gq];
        float cA1 = red[256 + 32 * wp + 16 + gq];
        float cB1 = red[256 + 32 * wp + 24 + gq];
#pragma unroll
        for (int t = 0; t < 8; ++t) {
            acc[0][t].x *= cA0; acc[0][t].y *= cA0;
            acc[0][t].z *= cB0; acc[0][t].w *= cB0;
            acc[1][t].x *= cA1; acc[1][t].y *= cA1;
            acc[1][t].z *= cB1; acc[1][t].w *= cB1;
        }

        // ---- O += P V (warp: 32 rows x 64 vcols) ----
#pragma unroll
        for (int kk = 0; kk < 4; ++kk) {
            u32 a00, a01, a02, a03, a10, a11, a12, a13;
            ldmx4(a00, a01, a02, a03, aP0 + kk * 32);
            ldmx4(a10, a11, a12, a13, aP1 + kk * 32);
            u32 vrow = aV + kk * (16 * V_S * 2);
#pragma unroll
            for (int p = 0; p < 4; ++p) {
                u32 b0, b1, b2, b3;
                ldmx4t(b0, b1, b2, b3, vrow + p * 32);
                mmabf(acc[0][2 * p], a00, a01, a02, a03, b0, b1);
                mmabf(acc[0][2 * p + 1], a00, a01, a02, a03, b2, b3);
                mmabf(acc[1][2 * p], a10, a11, a12, a13, b0, b1);
                mmabf(acc[1][2 * p + 1], a10, a11, a12, a13, b2, b3);
            }
        }
        __syncthreads();       // (4) Vh/Ph readers done

        // prefetch V(mb+1) (overlaps next tile's S)
        if (more) {
            const __nv_bfloat16* Vg = Vg0 + (size_t)(mb + 64) * DV;
#pragma unroll
            for (int it = 0; it < 8; ++it) {
                int r = rV + 8 * it;
                cp16(smbase + (OFF_V + r * V_S + cV) * 2, Vg + (size_t)r * DV + cV);
            }
            CP_COMMIT();
        }
    }

    // ---- epilogue: att = csum - acc / L ----
    if (wc == 0 && qd == 0) {
        red[320 + row0] = L0;
        red[320 + row0 + 8] = L1;
    }
    __syncthreads();
    float iA0 = 1.0f / red[320 + 32 * wp + gq];
    float iB0 = 1.0f / red[320 + 32 * wp + 8 + gq];
    float iA1 = 1.0f / red[320 + 32 * wp + 16 + gq];
    float iB1 = 1.0f / red[320 + 32 * wp + 24 + gq];
    const float* cs = csum + b * DV;
    float* og = att + ((size_t)b * NTOK + nbase) * DV;
#pragma unroll
    for (int f = 0; f < 2; ++f) {
        float ia = f ? iA1 : iA0;
        float ib = f ? iB1 : iB0;
        int ra = 32 * wp + 16 * f + gq;
#pragma unroll
        for (int t = 0; t < 8; ++t) {
            int col = 64 * wq + 8 * t + 2 * qd;
            float2 c0 = *(const float2*)&cs[col];
            float2 r0, r1;
            r0.x = c0.x - acc[f][t].x * ia;
            r0.y = c0.y - acc[f][t].y * ia;
            r1.x = c0.x - acc[f][t].z * ib;
            r1.y = c0.y - acc[f][t].w * ib;
            *(float2*)&og[(size_t)ra * DV + col] = r0;
            *(float2*)&og[(size_t)(ra + 8) * DV + col] = r1;
        }
    }
}

// out[b][o][n] = relu((sum_c Wp[o][c]*att[b][n][c] + bias[o])*sc[o] + tr[o])
__global__ __launch_bounds__(256)
void projf_kernel(const float* __restrict__ A, const float* __restrict__ W,
                  const float* __restrict__ bias, const float* __restrict__ sc,
                  const float* __restrict__ tr, float* __restrict__ out) {
    __shared__ float As[32 * 68];
    __shared__ float Ws[64 * 33];
    const int b = blockIdx.z;
    const int obase = blockIdx.y * 64;
    const int nbase = blockIdx.x * 64;
    const int tid = threadIdx.x;
    const int tx = tid & 15, ty = tid >> 4;
    const float* Ag = A + (size_t)b * NTOK * DV;

    u64 accp[4][2];
#pragma unroll
    for (int i = 0; i < 4; ++i) { accp[i][0] = 0ull; accp[i][1] = 0ull; }

    for (int c0 = 0; c0 < DV; c0 += 32) {
        __syncthreads();
#pragma unroll
        for (int it = 0; it < 2; ++it) {
            int idx = tid + it * 256;
            int n = idx >> 3, c4 = idx & 7;
            float4 v = *(const float4*)&Ag[(size_t)(nbase + n) * DV + c0 + c4 * 4];
            As[(c4 * 4 + 0) * 68 + n] = v.x;
            As[(c4 * 4 + 1) * 68 + n] = v.y;
            As[(c4 * 4 + 2) * 68 + n] = v.z;
            As[(c4 * 4 + 3) * 68 + n] = v.w;
        }
#pragma unroll
        for (int it = 0; it < 8; ++it) {
            int idx = tid + it * 256;
            int r = idx >> 5, c = idx & 31;
            Ws[r * 33 + c] = W[(size_t)(obase + r) * DV + c0 + c];
        }
        __syncthreads();
#pragma unroll 4
        for (int c = 0; c < 32; ++c) {
            ulonglong2 ap = *(const ulonglong2*)&As[c * 68 + 4 * tx];
#pragma unroll
            for (int i = 0; i < 4; ++i) {
                float w = Ws[(4 * ty + i) * 33 + c];
                u64 w2 = pack2(w, w);
                ffma2(accp[i][0], w2, ap.x);
                ffma2(accp[i][1], w2, ap.y);
            }
        }
    }
#pragma unroll
    for (int i = 0; i < 4; ++i) {
        int o = obase + 4 * ty + i;
        float bb = bias[o], ss = sc[o], tt = tr[o];
        float2 a0 = unpack2(accp[i][0]);
        float2 a1 = unpack2(accp[i][1]);
        float4 r;
        r.x = (a0.x + bb) * ss + tt; r.x = r.x > 0.f ? r.x : 0.f;
        r.y = (a0.y + bb) * ss + tt; r.y = r.y > 0.f ? r.y : 0.f;
        r.z = (a1.x + bb) * ss + tt; r.z = r.z > 0.f ? r.z : 0.f;
        r.w = (a1.y + bb) * ss + tt; r.w = r.w > 0.f ? r.w : 0.f;
        *(float4*)&out[((size_t)b * OUTC + o) * NTOK + nbase + 4 * tx] = r;
    }
}

extern "C" void kernel_launch(void* const* d_in, const int* in_sizes, int n_in,
                              void* d_out, int out_size) {
    const float* x1 = (const float*)d_in[0];
    const float* x2 = (const float*)d_in[1];
    const float* Wq = (const float*)d_in[2];
    const float* bq = (const float*)d_in[3];
    const float* sq = (const float*)d_in[4];
    const float* tq = (const float*)d_in[5];
    const float* Wk = (const float*)d_in[6];
    const float* bk = (const float*)d_in[7];
    const float* sk = (const float*)d_in[8];
    const float* tk = (const float*)d_in[9];
    const float* Wv = (const float*)d_in[10];
    const float* bv = (const float*)d_in[11];
    const float* sv = (const float*)d_in[12];
    const float* tv = (const float*)d_in[13];
    const float* Wp = (const float*)d_in[14];
    const float* bp = (const float*)d_in[15];
    const float* sp = (const float*)d_in[16];
    const float* tp = (const float*)d_in[17];
    float* out = (float*)d_out;

    __nv_bfloat16 *pQ, *pK, *pVh;
    float *pVf, *pAtt, *pCs;
    cudaGetSymbolAddress((void**)&pQ, g_Qh);
    cudaGetSymbolAddress((void**)&pK, g_Kh);
    cudaGetSymbolAddress((void**)&pVh, g_Vh);
    cudaGetSymbolAddress((void**)&pVf, g_Vf);
    cudaGetSymbolAddress((void**)&pAtt, g_att);
    cudaGetSymbolAddress((void**)&pCs, g_csum);

    const int SMEM_ATTN = (OFF_RED) * 2 + 384 * 4;  // 95232 + 1536 = 96768 B
    cudaFuncSetAttribute(attn_kernel, cudaFuncAttributeMaxDynamicSharedMemorySize, SMEM_ATTN);

    qkv_proj_kernel<<<dim3(NTOK / 64, BATCH, 4), 256>>>(
        x1, x2, Wq, bq, sq, tq, Wk, bk, sk, tk, Wv, bv, sv, tv, pQ, pK, pVh, pVf);
    zero_csum_kernel<<<1, BATCH * DV>>>();
    colsum_kernel<<<dim3(NTOK / 64, BATCH), 256>>>();
    attn_kernel<<<dim3(NTOK / 64, BATCH), 256, SMEM_ATTN>>>(pQ, pK, pVh, pCs, pAtt);
    projf_kernel<<<dim3(NTOK / 64, OUTC / 64, BATCH), 256>>>(pAtt, Wp, bp, sp, tp, out);
}

// round 8
// speedup vs baseline: 2.6255x; 1.2783x over previous
#include <cuda_runtime.h>
#include <cuda_bf16.h>
#include <cstdint>

#define NTOK 4096
#define BATCH 4
#define CIN 256
#define DI 128
#define DV 256
#define OUTC 256

typedef unsigned long long u64;
typedef uint32_t u32;

// ---------------- bf16 mma + ldmatrix ----------------
__device__ __forceinline__ void mmabf(float4& d, u32 a0, u32 a1, u32 a2, u32 a3,
                                      u32 b0, u32 b1) {
    asm volatile(
        "mma.sync.aligned.m16n8k16.row.col.f32.bf16.bf16.f32 "
        "{%0,%1,%2,%3}, {%4,%5,%6,%7}, {%8,%9}, {%0,%1,%2,%3};"
        : "+f"(d.x), "+f"(d.y), "+f"(d.z), "+f"(d.w)
        : "r"(a0), "r"(a1), "r"(a2), "r"(a3), "r"(b0), "r"(b1));
}
__device__ __forceinline__ void ldmx4(u32& r0, u32& r1, u32& r2, u32& r3, u32 a) {
    asm volatile("ldmatrix.sync.aligned.m8n8.x4.shared.b16 {%0,%1,%2,%3}, [%4];"
                 : "=r"(r0), "=r"(r1), "=r"(r2), "=r"(r3) : "r"(a));
}
__device__ __forceinline__ void ldmx4t(u32& r0, u32& r1, u32& r2, u32& r3, u32 a) {
    asm volatile("ldmatrix.sync.aligned.m8n8.x4.trans.shared.b16 {%0,%1,%2,%3}, [%4];"
                 : "=r"(r0), "=r"(r1), "=r"(r2), "=r"(r3) : "r"(a));
}
__device__ __forceinline__ u32 pkbf(float lo, float hi) {   // lo -> lower half
    u32 r; asm("cvt.rn.bf16x2.f32 %0, %1, %2;" : "=r"(r) : "f"(hi), "f"(lo)); return r;
}

// ---------------- cp.async helpers ----------------
__device__ __forceinline__ u32 smaddr(const void* p) {
    return (u32)__cvta_generic_to_shared(p);
}
__device__ __forceinline__ void cp16(u32 dst, const void* src) {
    asm volatile("cp.async.cg.shared.global [%0], [%1], 16;" :: "r"(dst), "l"(src));
}
#define CP_COMMIT() asm volatile("cp.async.commit_group;")
#define CP_WAIT1()  asm volatile("cp.async.wait_group 1;")
#define CP_WAIT0()  asm volatile("cp.async.wait_group 0;")

// ---------------- scratch ----------------
__device__ __nv_bfloat16 g_x1h[BATCH * CIN * NTOK];
__device__ __nv_bfloat16 g_x2h[BATCH * CIN * NTOK];
__device__ __nv_bfloat16 g_Wh[3 * 128 * 256];        // Wq, Wk, Wv (bf16)
__device__ __nv_bfloat16 g_Wph[256 * 256];           // Wp (bf16)
__device__ __nv_bfloat16 g_Qh[BATCH * NTOK * DI];    // pre-scaled by 128^-0.5
__device__ __nv_bfloat16 g_Kh[BATCH * NTOK * DI];
__device__ __nv_bfloat16 g_Vh[BATCH * NTOK * DV];    // [0:128)=v2, [128:256)=v1
__device__ __nv_bfloat16 g_corrh[BATCH * NTOK * DV]; // P·V/L (bf16)
__device__ float g_csum[BATCH * DV];
__device__ float g_base[BATCH * OUTC];               // Wp·csum + bp

// ---------------- tiny kernels ----------------
__global__ void zero_csum_kernel() { g_csum[threadIdx.x] = 0.0f; }

__global__ void cvt_x_kernel(const float* __restrict__ x1, const float* __restrict__ x2) {
    const float* src = blockIdx.y ? x2 : x1;
    __nv_bfloat16* dst = blockIdx.y ? g_x2h : g_x1h;
    int idx = (blockIdx.x * 256 + threadIdx.x) * 4;
    float4 v = *(const float4*)&src[idx];
    *(uint2*)&dst[idx] = make_uint2(pkbf(v.x, v.y), pkbf(v.z, v.w));
}

__global__ void cvt_w_kernel(const float* __restrict__ Wq, const float* __restrict__ Wk,
                             const float* __restrict__ Wv, const float* __restrict__ Wp) {
    int y = blockIdx.y;
    const float* src = (y == 0) ? Wq : (y == 1) ? Wk : (y == 2) ? Wv : Wp;
    __nv_bfloat16* dst = (y < 3) ? (g_Wh + y * 32768) : g_Wph;
    int n = (y < 3) ? 32768 : 65536;
    int idx = (blockIdx.x * 256 + threadIdx.x) * 4;
    if (idx < n) {
        float4 v = *(const float4*)&src[idx];
        *(uint2*)&dst[idx] = make_uint2(pkbf(v.x, v.y), pkbf(v.z, v.w));
    }
}

// base[b][o] = bp[o] + sum_c Wp[o][c] * csum[b][c]   (exact fp32)
__global__ void base_kernel(const float* __restrict__ Wp, const float* __restrict__ bp) {
    __shared__ float cs[256];
    int b = blockIdx.x, o = threadIdx.x;
    cs[o] = g_csum[b * DV + o];
    __syncthreads();
    float s = bp[o];
    const float* w = Wp + (size_t)o * 256;
#pragma unroll 8
    for (int c = 0; c < 256; ++c) s += w[c] * cs[c];
    g_base[b * OUTC + o] = s;
}

// ============================================================================
// QKV projection, bf16 tensor cores. Block: 64 n x 128 o, k=256.
// v[n,o] = sum_c x[c,n]*W[o,c].  A = x via ldmatrix.trans on [c][n];
// B = W via ldmatrix on [o][c].  8 warps = 4(n) x 2(o of 64).
// z: 0=Q(x1), 1=K(x2), 2=V(x2)->cols[0,128), 3=V(x1)->cols[128,256).
// z>=2 also accumulates column sums (csum) via smem+global atomics (fp32).
// ============================================================================
#define XS_S 72
#define WS_S 264
#define QK_OFFW 18432     // halves
#define QK_OFFC 52224     // halves (colacc floats after this)
#define SMEM_QKV (52224 * 2 + 512)

__global__ __launch_bounds__(256, 2)
void qkv_tc_kernel(const float* __restrict__ bq, const float* __restrict__ sq,
                   const float* __restrict__ tq,
                   const float* __restrict__ bk, const float* __restrict__ sk,
                   const float* __restrict__ tk,
                   const float* __restrict__ bv, const float* __restrict__ sv,
                   const float* __restrict__ tv) {
    extern __shared__ uint16_t qsm[];
    float* colacc = (float*)(qsm + QK_OFFC);
    const int z = blockIdx.z, b = blockIdx.y, nbase = blockIdx.x * 64;
    const int tid = threadIdx.x, lane = tid & 31, wid = tid >> 5;
    const int wn = wid & 3, wo = wid >> 2;
    const int gq = lane >> 2, qd = lane & 3;
    const __nv_bfloat16* xh = (z == 0 || z == 3) ? g_x1h : g_x2h;
    const __nv_bfloat16* wg = g_Wh + (z < 2 ? z : 2) * 32768;
    const float* bias = (z == 0) ? bq : (z == 1) ? bk : bv;
    const float* sc = (z == 0) ? sq : (z == 1) ? sk : sv;
    const float* tr = (z == 0) ? tq : (z == 1) ? tk : tv;
    const float prescale = (z == 0) ? 0.08838834764831845f : 1.0f;
    const u32 smbase = smaddr(qsm);

    if (tid < 128) colacc[tid] = 0.0f;

    // ---- one-shot loads: Xs [256c][64n], Ws [128o][256c] ----
    {
        const __nv_bfloat16* xg = xh + (size_t)b * CIN * NTOK + nbase;
        int seg = (tid & 7) * 8;
#pragma unroll
        for (int it = 0; it < 8; ++it) {
            int r = (tid >> 3) + 32 * it;
            cp16(smbase + (r * XS_S + seg) * 2, xg + (size_t)r * NTOK + seg);
        }
    }
    {
        int seg = (tid & 31) * 8;
#pragma unroll
        for (int it = 0; it < 16; ++it) {
            int r = (tid >> 5) + 8 * it;
            cp16(smbase + (QK_OFFW + r * WS_S + seg) * 2, wg + (size_t)r * 256 + seg);
        }
    }
    CP_COMMIT(); CP_WAIT0();
    __syncthreads();

    // A-from-trans (rows c, cols n); B non-trans (rows o, cols c)
    const u32 aX = smbase + ((((lane & 7) + ((lane >> 4) & 1) * 8)) * XS_S +
                             16 * wn + ((lane >> 3) & 1) * 8) * 2;
    const u32 aW = smbase + (QK_OFFW + (64 * wo + (lane & 7) + ((lane >> 4) & 1) * 8) * WS_S +
                             ((lane >> 3) & 1) * 8) * 2;

    float4 acc[8];
#pragma unroll
    for (int t = 0; t < 8; ++t) acc[t] = make_float4(0.f, 0.f, 0.f, 0.f);

#pragma unroll
    for (int kk = 0; kk < 16; ++kk) {
        u32 a0, a1, a2, a3;
        ldmx4t(a0, a1, a2, a3, aX + kk * 16 * XS_S * 2);
#pragma unroll
        for (int j = 0; j < 4; ++j) {
            u32 b0, b1, b2, b3;
            ldmx4(b0, b1, b2, b3, aW + (j * 16 * WS_S + kk * 16) * 2);
            mmabf(acc[2 * j], a0, a1, a2, a3, b0, b1);
            mmabf(acc[2 * j + 1], a0, a1, a2, a3, b2, b3);
        }
    }

    // ---- epilogue: affine + relu + prescale, bf16 stores, csum partials ----
    const int n0 = 16 * wn + gq;
    const size_t rg = (size_t)b * NTOK + nbase + n0;
#pragma unroll
    for (int t = 0; t < 8; ++t) {
        int o = 64 * wo + 8 * t + 2 * qd;
        float2 bb = *(const float2*)&bias[o];
        float2 ss = *(const float2*)&sc[o];
        float2 tt = *(const float2*)&tr[o];
        float v00 = fmaxf((acc[t].x + bb.x) * ss.x + tt.x, 0.f) * prescale;
        float v01 = fmaxf((acc[t].y + bb.y) * ss.y + tt.y, 0.f) * prescale;
        float v10 = fmaxf((acc[t].z + bb.x) * ss.x + tt.x, 0.f) * prescale;
        float v11 = fmaxf((acc[t].w + bb.y) * ss.y + tt.y, 0.f) * prescale;
        if (z == 0) {
            *(u32*)&g_Qh[rg * DI + o] = pkbf(v00, v01);
            *(u32*)&g_Qh[(rg + 8) * DI + o] = pkbf(v10, v11);
        } else if (z == 1) {
            *(u32*)&g_Kh[rg * DI + o] = pkbf(v00, v01);
            *(u32*)&g_Kh[(rg + 8) * DI + o] = pkbf(v10, v11);
        } else {
            int oc = o + (z == 3 ? 128 : 0);
            *(u32*)&g_Vh[rg * DV + oc] = pkbf(v00, v01);
            *(u32*)&g_Vh[(rg + 8) * DV + oc] = pkbf(v10, v11);
            atomicAdd(&colacc[o], v00 + v10);
            atomicAdd(&colacc[o + 1], v01 + v11);
        }
    }
    if (z >= 2) {
        __syncthreads();
        if (tid < 128) {
            int ofs = (z == 3) ? 128 : 0;
            atomicAdd(&g_csum[b * DV + ofs + tid], colacc[tid]);
        }
    }
}

// ============================================================================
// bf16 flash attention with complement; writes corr[n][c] = (P·V/L) in bf16.
// (identical mainloop to round 7; epilogue changed)
// ============================================================================
#define QK_S 136
#define V_S  264
#define P_S  72
#define OFF_K 8704
#define OFF_V 26112
#define OFF_P 43008
#define OFF_RED 47616
#define SMEM_ATTN (OFF_RED * 2 + 384 * 4)

__global__ __launch_bounds__(256, 2)
void attn_kernel() {
    extern __shared__ uint16_t smh[];
    float* red = (float*)(smh + OFF_RED);

    const int b = blockIdx.y;
    const int nbase = blockIdx.x * 64;
    const int tid = threadIdx.x;
    const int wid = tid >> 5, lane = tid & 31;
    const int wr = wid >> 1, wc = wid & 1;
    const int wp = wid >> 2, wq = wid & 3;
    const int gq = lane >> 2, qd = lane & 3;
    const int row0 = 16 * wr + gq;

    const int rK = tid >> 4, cK = (tid & 15) * 8;
    const int rV = tid >> 5, cV = (tid & 31) * 8;
    const __nv_bfloat16* Qg = g_Qh + ((size_t)b * NTOK + nbase) * DI;
    const __nv_bfloat16* Kg0 = g_Kh + (size_t)b * NTOK * DI;
    const __nv_bfloat16* Vg0 = g_Vh + (size_t)b * NTOK * DV;
    const u32 smbase = smaddr(smh);

#pragma unroll
    for (int it = 0; it < 4; ++it) {
        int r = rK + 16 * it;
        cp16(smbase + (r * QK_S + cK) * 2, Qg + (size_t)r * DI + cK);
        cp16(smbase + (OFF_K + r * QK_S + cK) * 2, Kg0 + (size_t)r * DI + cK);
    }
    CP_COMMIT();
#pragma unroll
    for (int it = 0; it < 8; ++it) {
        int r = rV + 8 * it;
        cp16(smbase + (OFF_V + r * V_S + cV) * 2, Vg0 + (size_t)r * DV + cV);
    }
    CP_COMMIT();

    const u32 aQ = smbase + ((16 * wr + (lane & 15)) * QK_S + (lane >> 4) * 8) * 2;
    const u32 aKoff = ((32 * wc + (lane & 7) + (lane >> 4) * 8) * QK_S +
                       ((lane >> 3) & 1) * 8) * 2;
    const u32 aP0 = smbase + (OFF_P + (32 * wp + (lane & 15)) * P_S + (lane >> 4) * 8) * 2;
    const u32 aP1 = aP0 + 16 * P_S * 2;
    const u32 aV = smbase + (OFF_V + ((lane & 7) + ((lane >> 3) & 1) * 8) * V_S +
                             64 * wq + (lane >> 4) * 8) * 2;

    float M0 = -1e30f, M1 = -1e30f, L0 = 0.0f, L1 = 0.0f;
    float4 acc[2][8];
#pragma unroll
    for (int f = 0; f < 2; ++f)
#pragma unroll
        for (int t = 0; t < 8; ++t) acc[f][t] = make_float4(0.f, 0.f, 0.f, 0.f);

    int par = 0;
    for (int mb = 0; mb < NTOK; mb += 64, par ^= 1) {
        const bool more = (mb + 64) < NTOK;
        CP_WAIT1();
        __syncthreads();

        if (more) {
            const __nv_bfloat16* Kg = Kg0 + (size_t)(mb + 64) * DI;
            u32 kd = smbase + (OFF_K + (par ^ 1) * 8704) * 2;
#pragma unroll
            for (int it = 0; it < 4; ++it) {
                int r = rK + 16 * it;
                cp16(kd + (r * QK_S + cK) * 2, Kg + (size_t)r * DI + cK);
            }
            CP_COMMIT();
        }

        float4 S[4];
#pragma unroll
        for (int t = 0; t < 4; ++t) S[t] = make_float4(0.f, 0.f, 0.f, 0.f);
        const u32 aK = smbase + (OFF_K + par * 8704) * 2 + aKoff;
        const u32 aK2 = aK + 16 * QK_S * 2;
#pragma unroll
        for (int kk = 0; kk < 8; ++kk) {
            u32 a0, a1, a2, a3, b00, b01, b10, b11, b20, b21, b30, b31;
            ldmx4(a0, a1, a2, a3, aQ + kk * 32);
            ldmx4(b00, b01, b10, b11, aK + kk * 32);
            ldmx4(b20, b21, b30, b31, aK2 + kk * 32);
            mmabf(S[0], a0, a1, a2, a3, b00, b01);
            mmabf(S[1], a0, a1, a2, a3, b10, b11);
            mmabf(S[2], a0, a1, a2, a3, b20, b21);
            mmabf(S[3], a0, a1, a2, a3, b30, b31);
        }

        float mx0 = fmaxf(fmaxf(S[0].x, S[0].y), fmaxf(S[1].x, S[1].y));
        mx0 = fmaxf(mx0, fmaxf(fmaxf(S[2].x, S[2].y), fmaxf(S[3].x, S[3].y)));
        float mx1 = fmaxf(fmaxf(S[0].z, S[0].w), fmaxf(S[1].z, S[1].w));
        mx1 = fmaxf(mx1, fmaxf(fmaxf(S[2].z, S[2].w), fmaxf(S[3].z, S[3].w)));
        mx0 = fmaxf(mx0, __shfl_xor_sync(0xffffffffu, mx0, 1));
        mx0 = fmaxf(mx0, __shfl_xor_sync(0xffffffffu, mx0, 2));
        mx1 = fmaxf(mx1, __shfl_xor_sync(0xffffffffu, mx1, 1));
        mx1 = fmaxf(mx1, __shfl_xor_sync(0xffffffffu, mx1, 2));
        if (qd == 0) {
            red[wc * 64 + row0] = mx0;
            red[wc * 64 + row0 + 8] = mx1;
        }
        __syncthreads();
        float newM0 = fmaxf(M0, fmaxf(red[row0], red[64 + row0]));
        float newM1 = fmaxf(M1, fmaxf(red[row0 + 8], red[64 + row0 + 8]));
        float corr0 = __expf(M0 - newM0);
        float corr1 = __expf(M1 - newM1);
        if (wc == 0 && qd == 0) {
            red[256 + row0] = corr0;
            red[256 + row0 + 8] = corr1;
        }

        float s0 = 0.0f, s1 = 0.0f;
#pragma unroll
        for (int t = 0; t < 4; ++t) {
            S[t].x = __expf(S[t].x - newM0);
            S[t].y = __expf(S[t].y - newM0);
            S[t].z = __expf(S[t].z - newM1);
            S[t].w = __expf(S[t].w - newM1);
            s0 += S[t].x + S[t].y;
            s1 += S[t].z + S[t].w;
            int col = 32 * wc + 8 * t + 2 * qd;
            *(u32*)(smh + OFF_P + row0 * P_S + col) = pkbf(S[t].x, S[t].y);
            *(u32*)(smh + OFF_P + (row0 + 8) * P_S + col) = pkbf(S[t].z, S[t].w);
        }
        s0 += __shfl_xor_sync(0xffffffffu, s0, 1);
        s0 += __shfl_xor_sync(0xffffffffu, s0, 2);
        s1 += __shfl_xor_sync(0xffffffffu, s1, 1);
        s1 += __shfl_xor_sync(0xffffffffu, s1, 2);
        if (qd == 0) {
            red[128 + wc * 64 + row0] = s0;
            red[128 + wc * 64 + row0 + 8] = s1;
        }
        if (more) CP_WAIT1(); else CP_WAIT0();
        __syncthreads();

        L0 = L0 * corr0 + red[128 + row0] + red[192 + row0];
        L1 = L1 * corr1 + red[128 + row0 + 8] + red[192 + row0 + 8];
        M0 = newM0; M1 = newM1;

        float cA0 = red[256 + 32 * wp + gq];
        float cB0 = red[256 + 32 * wp + 8 + gq];
        float cA1 = red[256 + 32 * wp + 16 + gq];
        float cB1 = red[256 + 32 * wp + 24 + gq];
#pragma unroll
        for (int t = 0; t < 8; ++t) {
            acc[0][t].x *= cA0; acc[0][t].y *= cA0;
            acc[0][t].z *= cB0; acc[0][t].w *= cB0;
            acc[1][t].x *= cA1; acc[1][t].y *= cA1;
            acc[1][t].z *= cB1; acc[1][t].w *= cB1;
        }

#pragma unroll
        for (int kk = 0; kk < 4; ++kk) {
            u32 a00, a01, a02, a03, a10, a11, a12, a13;
            ldmx4(a00, a01, a02, a03, aP0 + kk * 32);
            ldmx4(a10, a11, a12, a13, aP1 + kk * 32);
            u32 vrow = aV + kk * (16 * V_S * 2);
#pragma unroll
            for (int p = 0; p < 4; ++p) {
                u32 b0, b1, b2, b3;
                ldmx4t(b0, b1, b2, b3, vrow + p * 32);
                mmabf(acc[0][2 * p], a00, a01, a02, a03, b0, b1);
                mmabf(acc[0][2 * p + 1], a00, a01, a02, a03, b2, b3);
                mmabf(acc[1][2 * p], a10, a11, a12, a13, b0, b1);
                mmabf(acc[1][2 * p + 1], a10, a11, a12, a13, b2, b3);
            }
        }
        __syncthreads();

        if (more) {
            const __nv_bfloat16* Vg = Vg0 + (size_t)(mb + 64) * DV;
#pragma unroll
            for (int it = 0; it < 8; ++it) {
                int r = rV + 8 * it;
                cp16(smbase + (OFF_V + r * V_S + cV) * 2, Vg + (size_t)r * DV + cV);
            }
            CP_COMMIT();
        }
    }

    // ---- epilogue: corr = acc / L  (bf16) ----
    if (wc == 0 && qd == 0) {
        red[320 + row0] = L0;
        red[320 + row0 + 8] = L1;
    }
    __syncthreads();
    float iA0 = 1.0f / red[320 + 32 * wp + gq];
    float iB0 = 1.0f / red[320 + 32 * wp + 8 + gq];
    float iA1 = 1.0f / red[320 + 32 * wp + 16 + gq];
    float iB1 = 1.0f / red[320 + 32 * wp + 24 + gq];
    __nv_bfloat16* og = g_corrh + ((size_t)b * NTOK + nbase) * DV;
#pragma unroll
    for (int f = 0; f < 2; ++f) {
        float ia = f ? iA1 : iA0;
        float ib = f ? iB1 : iB0;
        int ra = 32 * wp + 16 * f + gq;
#pragma unroll
        for (int t = 0; t < 8; ++t) {
            int col = 64 * wq + 8 * t + 2 * qd;
            *(u32*)&og[(size_t)ra * DV + col] = pkbf(acc[f][t].x * ia, acc[f][t].y * ia);
            *(u32*)&og[(size_t)(ra + 8) * DV + col] = pkbf(acc[f][t].z * ib, acc[f][t].w * ib);
        }
    }
}

// ============================================================================
// Output projection, bf16 tensor cores with base subtraction.
// out[b][o][n] = relu((base[b][o] - sum_c Wp[o][c]*corr[n][c])*sp[o] + tp[o])
// Block: 128 o x 64 n, k=256. 8 warps, each 16 o x 64 n.
// ============================================================================
#define PF_OFFW 16896
#define SMEM_PF ((16896 + 33792) * 2)

__global__ __launch_bounds__(256, 2)
void projf_tc_kernel(const float* __restrict__ sp, const float* __restrict__ tp,
                     float* __restrict__ out) {
    extern __shared__ uint16_t psm[];
    const int b = blockIdx.z, obase = blockIdx.y * 128, nbase = blockIdx.x * 64;
    const int tid = threadIdx.x, lane = tid & 31, wid = tid >> 5;
    const int gq = lane >> 2, qd = lane & 3;
    const u32 smbase = smaddr(psm);

    {
        const __nv_bfloat16* cg = g_corrh + ((size_t)b * NTOK + nbase) * DV;
        int seg = (tid & 31) * 8;
#pragma unroll
        for (int it = 0; it < 8; ++it) {
            int r = (tid >> 5) + 8 * it;
            cp16(smbase + (r * WS_S + seg) * 2, cg + (size_t)r * DV + seg);
        }
        const __nv_bfloat16* wg = g_Wph + (size_t)obase * 256;
#pragma unroll
        for (int it = 0; it < 16; ++it) {
            int r = (tid >> 5) + 8 * it;
            cp16(smbase + (PF_OFFW + r * WS_S + seg) * 2, wg + (size_t)r * 256 + seg);
        }
    }
    CP_COMMIT(); CP_WAIT0();
    __syncthreads();

    const u32 aA = smbase + (PF_OFFW + (16 * wid + (lane & 15)) * WS_S + (lane >> 4) * 8) * 2;
    const u32 aB = smbase + (((lane & 7) + ((lane >> 4) & 1) * 8) * WS_S +
                             ((lane >> 3) & 1) * 8) * 2;

    float4 acc[8];
#pragma unroll
    for (int t = 0; t < 8; ++t) acc[t] = make_float4(0.f, 0.f, 0.f, 0.f);

#pragma unroll
    for (int kk = 0; kk < 16; ++kk) {
        u32 a0, a1, a2, a3;
        ldmx4(a0, a1, a2, a3, aA + kk * 16 * 2);
#pragma unroll
        for (int j = 0; j < 4; ++j) {
            u32 b0, b1, b2, b3;
            ldmx4(b0, b1, b2, b3, aB + (j * 16 * WS_S + kk * 16) * 2);
            mmabf(acc[2 * j], a0, a1, a2, a3, b0, b1);
            mmabf(acc[2 * j + 1], a0, a1, a2, a3, b2, b3);
        }
    }

    const int o0 = obase + 16 * wid + gq;
    float bs0 = g_base[b * OUTC + o0], bs1 = g_base[b * OUTC + o0 + 8];
    float sp0 = sp[o0], sp1 = sp[o0 + 8], tp0 = tp[o0], tp1 = tp[o0 + 8];
    float* og0 = out + ((size_t)b * OUTC + o0) * NTOK + nbase;
    float* og1 = og0 + (size_t)8 * NTOK;
#pragma unroll
    for (int t = 0; t < 8; ++t) {
        int n = 8 * t + 2 * qd;
        float2 r0, r1;
        r0.x = fmaxf((bs0 - acc[t].x) * sp0 + tp0, 0.f);
        r0.y = fmaxf((bs0 - acc[t].y) * sp0 + tp0, 0.f);
        r1.x = fmaxf((bs1 - acc[t].z) * sp1 + tp1, 0.f);
        r1.y = fmaxf((bs1 - acc[t].w) * sp1 + tp1, 0.f);
        *(float2*)&og0[n] = r0;
        *(float2*)&og1[n] = r1;
    }
}

extern "C" void kernel_launch(void* const* d_in, const int* in_sizes, int n_in,
                              void* d_out, int out_size) {
    const float* x1 = (const float*)d_in[0];
    const float* x2 = (const float*)d_in[1];
    const float* Wq = (const float*)d_in[2];
    const float* bq = (const float*)d_in[3];
    const float* sq = (const float*)d_in[4];
    const float* tq = (const float*)d_in[5];
    const float* Wk = (const float*)d_in[6];
    const float* bk = (const float*)d_in[7];
    const float* sk = (const float*)d_in[8];
    const float* tk = (const float*)d_in[9];
    const float* Wv = (const float*)d_in[10];
    const float* bv = (const float*)d_in[11];
    const float* sv = (const float*)d_in[12];
    const float* tv = (const float*)d_in[13];
    const float* Wp = (const float*)d_in[14];
    const float* bp = (const float*)d_in[15];
    const float* sp = (const float*)d_in[16];
    const float* tp = (const float*)d_in[17];
    float* out = (float*)d_out;

    cudaFuncSetAttribute(qkv_tc_kernel, cudaFuncAttributeMaxDynamicSharedMemorySize, SMEM_QKV);
    cudaFuncSetAttribute(attn_kernel, cudaFuncAttributeMaxDynamicSharedMemorySize, SMEM_ATTN);
    cudaFuncSetAttribute(projf_tc_kernel, cudaFuncAttributeMaxDynamicSharedMemorySize, SMEM_PF);

    cvt_x_kernel<<<dim3(4096, 2), 256>>>(x1, x2);
    cvt_w_kernel<<<dim3(64, 4), 256>>>(Wq, Wk, Wv, Wp);
    zero_csum_kernel<<<1, BATCH * DV>>>();
    qkv_tc_kernel<<<dim3(NTOK / 64, BATCH, 4), 256, SMEM_QKV>>>(
        bq, sq, tq, bk, sk, tk, bv, sv, tv);
    base_kernel<<<BATCH, 256>>>(Wp, bp);
    attn_kernel<<<dim3(NTOK / 64, BATCH), 256, SMEM_ATTN>>>();
    projf_tc_kernel<<<dim3(NTOK / 64, OUTC / 128, BATCH), 256, SMEM_PF>>>(sp, tp, out);
}

// round 9
// speedup vs baseline: 2.6258x; 1.0001x over previous
#include <cuda_runtime.h>
#include <cuda_bf16.h>
#include <cstdint>

#define NTOK 4096
#define BATCH 4
#define CIN 256
#define DI 128
#define DV 256
#define OUTC 256

typedef unsigned long long u64;
typedef uint32_t u32;

// ---------------- bf16 mma + ldmatrix ----------------
__device__ __forceinline__ void mmabf(float4& d, u32 a0, u32 a1, u32 a2, u32 a3,
                                      u32 b0, u32 b1) {
    asm volatile(
        "mma.sync.aligned.m16n8k16.row.col.f32.bf16.bf16.f32 "
        "{%0,%1,%2,%3}, {%4,%5,%6,%7}, {%8,%9}, {%0,%1,%2,%3};"
        : "+f"(d.x), "+f"(d.y), "+f"(d.z), "+f"(d.w)
        : "r"(a0), "r"(a1), "r"(a2), "r"(a3), "r"(b0), "r"(b1));
}
__device__ __forceinline__ void ldmx4(u32& r0, u32& r1, u32& r2, u32& r3, u32 a) {
    asm volatile("ldmatrix.sync.aligned.m8n8.x4.shared.b16 {%0,%1,%2,%3}, [%4];"
                 : "=r"(r0), "=r"(r1), "=r"(r2), "=r"(r3) : "r"(a));
}
__device__ __forceinline__ void ldmx4t(u32& r0, u32& r1, u32& r2, u32& r3, u32 a) {
    asm volatile("ldmatrix.sync.aligned.m8n8.x4.trans.shared.b16 {%0,%1,%2,%3}, [%4];"
                 : "=r"(r0), "=r"(r1), "=r"(r2), "=r"(r3) : "r"(a));
}
__device__ __forceinline__ u32 pkbf(float lo, float hi) {   // lo -> lower half
    u32 r; asm("cvt.rn.bf16x2.f32 %0, %1, %2;" : "=r"(r) : "f"(hi), "f"(lo)); return r;
}

// ---------------- cp.async helpers ----------------
__device__ __forceinline__ u32 smaddr(const void* p) {
    return (u32)__cvta_generic_to_shared(p);
}
__device__ __forceinline__ void cp16(u32 dst, const void* src) {
    asm volatile("cp.async.cg.shared.global [%0], [%1], 16;" :: "r"(dst), "l"(src));
}
#define CP_COMMIT() asm volatile("cp.async.commit_group;")
#define CP_WAIT1()  asm volatile("cp.async.wait_group 1;")
#define CP_WAIT0()  asm volatile("cp.async.wait_group 0;")

// ---------------- scratch ----------------
__device__ __nv_bfloat16 g_x1h[BATCH * CIN * NTOK];
__device__ __nv_bfloat16 g_x2h[BATCH * CIN * NTOK];
__device__ __nv_bfloat16 g_Wh[3 * 128 * 256];        // Wq, Wk, Wv (bf16)
__device__ __nv_bfloat16 g_Wph[256 * 256];           // Wp (bf16)
__device__ __nv_bfloat16 g_Qh[BATCH * NTOK * DI];    // pre-scaled by 128^-0.5
__device__ __nv_bfloat16 g_Kh[BATCH * NTOK * DI];
__device__ __nv_bfloat16 g_Vh[BATCH * NTOK * DV];    // [0:128)=v2, [128:256)=v1
__device__ __nv_bfloat16 g_corrh[BATCH * NTOK * DV]; // P·V/L (bf16)
__device__ float g_csum[BATCH * DV];
__device__ float g_base[BATCH * OUTC];               // Wp·csum + bp

// ---------------- tiny kernels ----------------
__global__ void zero_csum_kernel() { g_csum[threadIdx.x] = 0.0f; }

__global__ void cvt_x_kernel(const float* __restrict__ x1, const float* __restrict__ x2) {
    const float* src = blockIdx.y ? x2 : x1;
    __nv_bfloat16* dst = blockIdx.y ? g_x2h : g_x1h;
    int idx = (blockIdx.x * 256 + threadIdx.x) * 4;
    float4 v = *(const float4*)&src[idx];
    *(uint2*)&dst[idx] = make_uint2(pkbf(v.x, v.y), pkbf(v.z, v.w));
}

__global__ void cvt_w_kernel(const float* __restrict__ Wq, const float* __restrict__ Wk,
                             const float* __restrict__ Wv, const float* __restrict__ Wp) {
    int y = blockIdx.y;
    const float* src = (y == 0) ? Wq : (y == 1) ? Wk : (y == 2) ? Wv : Wp;
    __nv_bfloat16* dst = (y < 3) ? (g_Wh + y * 32768) : g_Wph;
    int n = (y < 3) ? 32768 : 65536;
    int idx = (blockIdx.x * 256 + threadIdx.x) * 4;
    if (idx < n) {
        float4 v = *(const float4*)&src[idx];
        *(uint2*)&dst[idx] = make_uint2(pkbf(v.x, v.y), pkbf(v.z, v.w));
    }
}

// base[b][o] = bp[o] + sum_c Wp[o][c] * csum[b][c]   (exact fp32)
__global__ void base_kernel(const float* __restrict__ Wp, const float* __restrict__ bp) {
    __shared__ float cs[256];
    int b = blockIdx.x, o = threadIdx.x;
    cs[o] = g_csum[b * DV + o];
    __syncthreads();
    float s = bp[o];
    const float* w = Wp + (size_t)o * 256;
#pragma unroll 8
    for (int c = 0; c < 256; ++c) s += w[c] * cs[c];
    g_base[b * OUTC + o] = s;
}

// ============================================================================
// QKV projection, bf16 tensor cores. Block: 64 n x 128 o, k=256.
// v[n,o] = sum_c x[c,n]*W[o,c].  A = x via ldmatrix.trans on [c][n];
// B = W via ldmatrix on [o][c].  8 warps = 4(n) x 2(o of 64).
// z: 0=Q(x1), 1=K(x2), 2=V(x2)->cols[0,128), 3=V(x1)->cols[128,256).
// z>=2 also accumulates column sums (csum) via smem+global atomics (fp32).
// ============================================================================
#define XS_S 72
#define WS_S 264
#define QK_OFFW 18432     // halves
#define QK_OFFC 52224     // halves (colacc floats after this)
#define SMEM_QKV (52224 * 2 + 512)

__global__ __launch_bounds__(256, 2)
void qkv_tc_kernel(const float* __restrict__ bq, const float* __restrict__ sq,
                   const float* __restrict__ tq,
                   const float* __restrict__ bk, const float* __restrict__ sk,
                   const float* __restrict__ tk,
                   const float* __restrict__ bv, const float* __restrict__ sv,
                   const float* __restrict__ tv) {
    extern __shared__ uint16_t qsm[];
    float* colacc = (float*)(qsm + QK_OFFC);
    const int z = blockIdx.z, b = blockIdx.y, nbase = blockIdx.x * 64;
    const int tid = threadIdx.x, lane = tid & 31, wid = tid >> 5;
    const int wn = wid & 3, wo = wid >> 2;
    const int gq = lane >> 2, qd = lane & 3;
    const __nv_bfloat16* xh = (z == 0 || z == 3) ? g_x1h : g_x2h;
    const __nv_bfloat16* wg = g_Wh + (z < 2 ? z : 2) * 32768;
    const float* bias = (z == 0) ? bq : (z == 1) ? bk : bv;
    const float* sc = (z == 0) ? sq : (z == 1) ? sk : sv;
    const float* tr = (z == 0) ? tq : (z == 1) ? tk : tv;
    const float prescale = (z == 0) ? 0.08838834764831845f : 1.0f;
    const u32 smbase = smaddr(qsm);

    if (tid < 128) colacc[tid] = 0.0f;

    // ---- one-shot loads: Xs [256c][64n], Ws [128o][256c] ----
    {
        const __nv_bfloat16* xg = xh + (size_t)b * CIN * NTOK + nbase;
        int seg = (tid & 7) * 8;
#pragma unroll
        for (int it = 0; it < 8; ++it) {
            int r = (tid >> 3) + 32 * it;
            cp16(smbase + (r * XS_S + seg) * 2, xg + (size_t)r * NTOK + seg);
        }
    }
    {
        int seg = (tid & 31) * 8;
#pragma unroll
        for (int it = 0; it < 16; ++it) {
            int r = (tid >> 5) + 8 * it;
            cp16(smbase + (QK_OFFW + r * WS_S + seg) * 2, wg + (size_t)r * 256 + seg);
        }
    }
    CP_COMMIT(); CP_WAIT0();
    __syncthreads();

    // A-from-trans (rows c, cols n); B non-trans (rows o, cols c)
    const u32 aX = smbase + ((((lane & 7) + ((lane >> 4) & 1) * 8)) * XS_S +
                             16 * wn + ((lane >> 3) & 1) * 8) * 2;
    const u32 aW = smbase + (QK_OFFW + (64 * wo + (lane & 7) + ((lane >> 4) & 1) * 8) * WS_S +
                             ((lane >> 3) & 1) * 8) * 2;

    float4 acc[8];
#pragma unroll
    for (int t = 0; t < 8; ++t) acc[t] = make_float4(0.f, 0.f, 0.f, 0.f);

#pragma unroll
    for (int kk = 0; kk < 16; ++kk) {
        u32 a0, a1, a2, a3;
        ldmx4t(a0, a1, a2, a3, aX + kk * 16 * XS_S * 2);
#pragma unroll
        for (int j = 0; j < 4; ++j) {
            u32 b0, b1, b2, b3;
            ldmx4(b0, b1, b2, b3, aW + (j * 16 * WS_S + kk * 16) * 2);
            mmabf(acc[2 * j], a0, a1, a2, a3, b0, b1);
            mmabf(acc[2 * j + 1], a0, a1, a2, a3, b2, b3);
        }
    }

    // ---- epilogue: affine + relu + prescale, bf16 stores, csum partials ----
    const int n0 = 16 * wn + gq;
    const size_t rg = (size_t)b * NTOK + nbase + n0;
#pragma unroll
    for (int t = 0; t < 8; ++t) {
        int o = 64 * wo + 8 * t + 2 * qd;
        float2 bb = *(const float2*)&bias[o];
        float2 ss = *(const float2*)&sc[o];
        float2 tt = *(const float2*)&tr[o];
        float v00 = fmaxf((acc[t].x + bb.x) * ss.x + tt.x, 0.f) * prescale;
        float v01 = fmaxf((acc[t].y + bb.y) * ss.y + tt.y, 0.f) * prescale;
        float v10 = fmaxf((acc[t].z + bb.x) * ss.x + tt.x, 0.f) * prescale;
        float v11 = fmaxf((acc[t].w + bb.y) * ss.y + tt.y, 0.f) * prescale;
        if (z == 0) {
            *(u32*)&g_Qh[rg * DI + o] = pkbf(v00, v01);
            *(u32*)&g_Qh[(rg + 8) * DI + o] = pkbf(v10, v11);
        } else if (z == 1) {
            *(u32*)&g_Kh[rg * DI + o] = pkbf(v00, v01);
            *(u32*)&g_Kh[(rg + 8) * DI + o] = pkbf(v10, v11);
        } else {
            int oc = o + (z == 3 ? 128 : 0);
            *(u32*)&g_Vh[rg * DV + oc] = pkbf(v00, v01);
            *(u32*)&g_Vh[(rg + 8) * DV + oc] = pkbf(v10, v11);
            atomicAdd(&colacc[o], v00 + v10);
            atomicAdd(&colacc[o + 1], v01 + v11);
        }
    }
    if (z >= 2) {
        __syncthreads();
        if (tid < 128) {
            int ofs = (z == 3) ? 128 : 0;
            atomicAdd(&g_csum[b * DV + ofs + tid], colacc[tid]);
        }
    }
}

// ============================================================================
// bf16 flash attention with complement; writes corr[n][c] = (P·V/L) in bf16.
// (identical mainloop to round 7; epilogue changed)
// ============================================================================
#define QK_S 136
#define V_S  264
#define P_S  72
#define OFF_K 8704
#define OFF_V 26112
#define OFF_P 43008
#define OFF_RED 47616
#define SMEM_ATTN (OFF_RED * 2 + 384 * 4)

__global__ __launch_bounds__(256, 2)
void attn_kernel() {
    extern __shared__ uint16_t smh[];
    float* red = (float*)(smh + OFF_RED);

    const int b = blockIdx.y;
    const int nbase = blockIdx.x * 64;
    const int tid = threadIdx.x;
    const int wid = tid >> 5, lane = tid & 31;
    const int wr = wid >> 1, wc = wid & 1;
    const int wp = wid >> 2, wq = wid & 3;
    const int gq = lane >> 2, qd = lane & 3;
    const int row0 = 16 * wr + gq;

    const int rK = tid >> 4, cK = (tid & 15) * 8;
    const int rV = tid >> 5, cV = (tid & 31) * 8;
    const __nv_bfloat16* Qg = g_Qh + ((size_t)b * NTOK + nbase) * DI;
    const __nv_bfloat16* Kg0 = g_Kh + (size_t)b * NTOK * DI;
    const __nv_bfloat16* Vg0 = g_Vh + (size_t)b * NTOK * DV;
    const u32 smbase = smaddr(smh);

#pragma unroll
    for (int it = 0; it < 4; ++it) {
        int r = rK + 16 * it;
        cp16(smbase + (r * QK_S + cK) * 2, Qg + (size_t)r * DI + cK);
        cp16(smbase + (OFF_K + r * QK_S + cK) * 2, Kg0 + (size_t)r * DI + cK);
    }
    CP_COMMIT();
#pragma unroll
    for (int it = 0; it < 8; ++it) {
        int r = rV + 8 * it;
        cp16(smbase + (OFF_V + r * V_S + cV) * 2, Vg0 + (size_t)r * DV + cV);
    }
    CP_COMMIT();

    const u32 aQ = smbase + ((16 * wr + (lane & 15)) * QK_S + (lane >> 4) * 8) * 2;
    const u32 aKoff = ((32 * wc + (lane & 7) + (lane >> 4) * 8) * QK_S +
                       ((lane >> 3) & 1) * 8) * 2;
    const u32 aP0 = smbase + (OFF_P + (32 * wp + (lane & 15)) * P_S + (lane >> 4) * 8) * 2;
    const u32 aP1 = aP0 + 16 * P_S * 2;
    const u32 aV = smbase + (OFF_V + ((lane & 7) + ((lane >> 3) & 1) * 8) * V_S +
                             64 * wq + (lane >> 4) * 8) * 2;

    float M0 = -1e30f, M1 = -1e30f, L0 = 0.0f, L1 = 0.0f;
    float4 acc[2][8];
#pragma unroll
    for (int f = 0; f < 2; ++f)
#pragma unroll
        for (int t = 0; t < 8; ++t) acc[f][t] = make_float4(0.f, 0.f, 0.f, 0.f);

    int par = 0;
    for (int mb = 0; mb < NTOK; mb += 64, par ^= 1) {
        const bool more = (mb + 64) < NTOK;
        CP_WAIT1();
        __syncthreads();

        if (more) {
            const __nv_bfloat16* Kg = Kg0 + (size_t)(mb + 64) * DI;
            u32 kd = smbase + (OFF_K + (par ^ 1) * 8704) * 2;
#pragma unroll
            for (int it = 0; it < 4; ++it) {
                int r = rK + 16 * it;
                cp16(kd + (r * QK_S + cK) * 2, Kg + (size_t)r * DI + cK);
            }
            CP_COMMIT();
        }

        float4 S[4];
#pragma unroll
        for (int t = 0; t < 4; ++t) S[t] = make_float4(0.f, 0.f, 0.f, 0.f);
        const u32 aK = smbase + (OFF_K + par * 8704) * 2 + aKoff;
        const u32 aK2 = aK + 16 * QK_S * 2;
#pragma unroll
        for (int kk = 0; kk < 8; ++kk) {
            u32 a0, a1, a2, a3, b00, b01, b10, b11, b20, b21, b30, b31;
            ldmx4(a0, a1, a2, a3, aQ + kk * 32);
            ldmx4(b00, b01, b10, b11, aK + kk * 32);
            ldmx4(b20, b21, b30, b31, aK2 + kk * 32);
            mmabf(S[0], a0, a1, a2, a3, b00, b01);
            mmabf(S[1], a0, a1, a2, a3, b10, b11);
            mmabf(S[2], a0, a1, a2, a3, b20, b21);
            mmabf(S[3], a0, a1, a2, a3, b30, b31);
        }

        float mx0 = fmaxf(fmaxf(S[0].x, S[0].y), fmaxf(S[1].x, S[1].y));
        mx0 = fmaxf(mx0, fmaxf(fmaxf(S[2].x, S[2].y), fmaxf(S[3].x, S[3].y)));
        float mx1 = fmaxf(fmaxf(S[0].z, S[0].w), fmaxf(S[1].z, S[1].w));
        mx1 = fmaxf(mx1, fmaxf(fmaxf(S[2].z, S[2].w), fmaxf(S[3].z, S[3].w)));
        mx0 = fmaxf(mx0, __shfl_xor_sync(0xffffffffu, mx0, 1));
        mx0 = fmaxf(mx0, __shfl_xor_sync(0xffffffffu, mx0, 2));
        mx1 = fmaxf(mx1, __shfl_xor_sync(0xffffffffu, mx1, 1));
        mx1 = fmaxf(mx1, __shfl_xor_sync(0xffffffffu, mx1, 2));
        if (qd == 0) {
            red[wc * 64 + row0] = mx0;
            red[wc * 64 + row0 + 8] = mx1;
        }
        __syncthreads();
        float newM0 = fmaxf(M0, fmaxf(red[row0], red[64 + row0]));
        float newM1 = fmaxf(M1, fmaxf(red[row0 + 8], red[64 + row0 + 8]));
        float corr0 = __expf(M0 - newM0);
        float corr1 = __expf(M1 - newM1);
        if (wc == 0 && qd == 0) {
            red[256 + row0] = corr0;
            red[256 + row0 + 8] = corr1;
        }

        float s0 = 0.0f, s1 = 0.0f;
#pragma unroll
        for (int t = 0; t < 4; ++t) {
            S[t].x = __expf(S[t].x - newM0);
            S[t].y = __expf(S[t].y - newM0);
            S[t].z = __expf(S[t].z - newM1);
            S[t].w = __expf(S[t].w - newM1);
            s0 += S[t].x + S[t].y;
            s1 += S[t].z + S[t].w;
            int col = 32 * wc + 8 * t + 2 * qd;
            *(u32*)(smh + OFF_P + row0 * P_S + col) = pkbf(S[t].x, S[t].y);
            *(u32*)(smh + OFF_P + (row0 + 8) * P_S + col) = pkbf(S[t].z, S[t].w);
        }
        s0 += __shfl_xor_sync(0xffffffffu, s0, 1);
        s0 += __shfl_xor_sync(0xffffffffu, s0, 2);
        s1 += __shfl_xor_sync(0xffffffffu, s1, 1);
        s1 += __shfl_xor_sync(0xffffffffu, s1, 2);
        if (qd == 0) {
            red[128 + wc * 64 + row0] = s0;
            red[128 + wc * 64 + row0 + 8] = s1;
        }
        if (more) CP_WAIT1(); else CP_WAIT0();
        __syncthreads();

        L0 = L0 * corr0 + red[128 + row0] + red[192 + row0];
        L1 = L1 * corr1 + red[128 + row0 + 8] + red[192 + row0 + 8];
        M0 = newM0; M1 = newM1;

        float cA0 = red[256 + 32 * wp + gq];
        float cB0 = red[256 + 32 * wp + 8 + gq];
        float cA1 = red[256 + 32 * wp + 16 + gq];
        float cB1 = red[256 + 32 * wp + 24 + gq];
#pragma unroll
        for (int t = 0; t < 8; ++t) {
            acc[0][t].x *= cA0; acc[0][t].y *= cA0;
            acc[0][t].z *= cB0; acc[0][t].w *= cB0;
            acc[1][t].x *= cA1; acc[1][t].y *= cA1;
            acc[1][t].z *= cB1; acc[1][t].w *= cB1;
        }

#pragma unroll
        for (int kk = 0; kk < 4; ++kk) {
            u32 a00, a01, a02, a03, a10, a11, a12, a13;
            ldmx4(a00, a01, a02, a03, aP0 + kk * 32);
            ldmx4(a10, a11, a12, a13, aP1 + kk * 32);
            u32 vrow = aV + kk * (16 * V_S * 2);
#pragma unroll
            for (int p = 0; p < 4; ++p) {
                u32 b0, b1, b2, b3;
                ldmx4t(b0, b1, b2, b3, vrow + p * 32);
                mmabf(acc[0][2 * p], a00, a01, a02, a03, b0, b1);
                mmabf(acc[0][2 * p + 1], a00, a01, a02, a03, b2, b3);
                mmabf(acc[1][2 * p], a10, a11, a12, a13, b0, b1);
                mmabf(acc[1][2 * p + 1], a10, a11, a12, a13, b2, b3);
            }
        }
        __syncthreads();

        if (more) {
            const __nv_bfloat16* Vg = Vg0 + (size_t)(mb + 64) * DV;
#pragma unroll
            for (int it = 0; it < 8; ++it) {
                int r = rV + 8 * it;
                cp16(smbase + (OFF_V + r * V_S + cV) * 2, Vg + (size_t)r * DV + cV);
            }
            CP_COMMIT();
        }
    }

    // ---- epilogue: corr = acc / L  (bf16) ----
    if (wc == 0 && qd == 0) {
        red[320 + row0] = L0;
        red[320 + row0 + 8] = L1;
    }
    __syncthreads();
    float iA0 = 1.0f / red[320 + 32 * wp + gq];
    float iB0 = 1.0f / red[320 + 32 * wp + 8 + gq];
    float iA1 = 1.0f / red[320 + 32 * wp + 16 + gq];
    float iB1 = 1.0f / red[320 + 32 * wp + 24 + gq];
    __nv_bfloat16* og = g_corrh + ((size_t)b * NTOK + nbase) * DV;
#pragma unroll
    for (int f = 0; f < 2; ++f) {
        float ia = f ? iA1 : iA0;
        float ib = f ? iB1 : iB0;
        int ra = 32 * wp + 16 * f + gq;
#pragma unroll
        for (int t = 0; t < 8; ++t) {
            int col = 64 * wq + 8 * t + 2 * qd;
            *(u32*)&og[(size_t)ra * DV + col] = pkbf(acc[f][t].x * ia, acc[f][t].y * ia);
            *(u32*)&og[(size_t)(ra + 8) * DV + col] = pkbf(acc[f][t].z * ib, acc[f][t].w * ib);
        }
    }
}

// ============================================================================
// Output projection, bf16 tensor cores with base subtraction.
// out[b][o][n] = relu((base[b][o] - sum_c Wp[o][c]*corr[n][c])*sp[o] + tp[o])
// Block: 128 o x 64 n, k=256. 8 warps, each 16 o x 64 n.
// ============================================================================
#define PF_OFFW 16896
#define SMEM_PF ((16896 + 33792) * 2)

__global__ __launch_bounds__(256, 2)
void projf_tc_kernel(const float* __restrict__ sp, const float* __restrict__ tp,
                     float* __restrict__ out) {
    extern __shared__ uint16_t psm[];
    const int b = blockIdx.z, obase = blockIdx.y * 128, nbase = blockIdx.x * 64;
    const int tid = threadIdx.x, lane = tid & 31, wid = tid >> 5;
    const int gq = lane >> 2, qd = lane & 3;
    const u32 smbase = smaddr(psm);

    {
        const __nv_bfloat16* cg = g_corrh + ((size_t)b * NTOK + nbase) * DV;
        int seg = (tid & 31) * 8;
#pragma unroll
        for (int it = 0; it < 8; ++it) {
            int r = (tid >> 5) + 8 * it;
            cp16(smbase + (r * WS_S + seg) * 2, cg + (size_t)r * DV + seg);
        }
        const __nv_bfloat16* wg = g_Wph + (size_t)obase * 256;
#pragma unroll
        for (int it = 0; it < 16; ++it) {
            int r = (tid >> 5) + 8 * it;
            cp16(smbase + (PF_OFFW + r * WS_S + seg) * 2, wg + (size_t)r * 256 + seg);
        }
    }
    CP_COMMIT(); CP_WAIT0();
    __syncthreads();

    const u32 aA = smbase + (PF_OFFW + (16 * wid + (lane & 15)) * WS_S + (lane >> 4) * 8) * 2;
    const u32 aB = smbase + (((lane & 7) + ((lane >> 4) & 1) * 8) * WS_S +
                             ((lane >> 3) & 1) * 8) * 2;

    float4 acc[8];
#pragma unroll
    for (int t = 0; t < 8; ++t) acc[t] = make_float4(0.f, 0.f, 0.f, 0.f);

#pragma unroll
    for (int kk = 0; kk < 16; ++kk) {
        u32 a0, a1, a2, a3;
        ldmx4(a0, a1, a2, a3, aA + kk * 16 * 2);
#pragma unroll
        for (int j = 0; j < 4; ++j) {
            u32 b0, b1, b2, b3;
            ldmx4(b0, b1, b2, b3, aB + (j * 16 * WS_S + kk * 16) * 2);
            mmabf(acc[2 * j], a0, a1, a2, a3, b0, b1);
            mmabf(acc[2 * j + 1], a0, a1, a2, a3, b2, b3);
        }
    }

    const int o0 = obase + 16 * wid + gq;
    float bs0 = g_base[b * OUTC + o0], bs1 = g_base[b * OUTC + o0 + 8];
    float sp0 = sp[o0], sp1 = sp[o0 + 8], tp0 = tp[o0], tp1 = tp[o0 + 8];
    float* og0 = out + ((size_t)b * OUTC + o0) * NTOK + nbase;
    float* og1 = og0 + (size_t)8 * NTOK;
#pragma unroll
    for (int t = 0; t < 8; ++t) {
        int n = 8 * t + 2 * qd;
        float2 r0, r1;
        r0.x = fmaxf((bs0 - acc[t].x) * sp0 + tp0, 0.f);
        r0.y = fmaxf((bs0 - acc[t].y) * sp0 + tp0, 0.f);
        r1.x = fmaxf((bs1 - acc[t].z) * sp1 + tp1, 0.f);
        r1.y = fmaxf((bs1 - acc[t].w) * sp1 + tp1, 0.f);
        *(float2*)&og0[n] = r0;
        *(float2*)&og1[n] = r1;
    }
}

extern "C" void kernel_launch(void* const* d_in, const int* in_sizes, int n_in,
                              void* d_out, int out_size) {
    const float* x1 = (const float*)d_in[0];
    const float* x2 = (const float*)d_in[1];
    const float* Wq = (const float*)d_in[2];
    const float* bq = (const float*)d_in[3];
    const float* sq = (const float*)d_in[4];
    const float* tq = (const float*)d_in[5];
    const float* Wk = (const float*)d_in[6];
    const float* bk = (const float*)d_in[7];
    const float* sk = (const float*)d_in[8];
    const float* tk = (const float*)d_in[9];
    const float* Wv = (const float*)d_in[10];
    const float* bv = (const float*)d_in[11];
    const float* sv = (const float*)d_in[12];
    const float* tv = (const float*)d_in[13];
    const float* Wp = (const float*)d_in[14];
    const float* bp = (const float*)d_in[15];
    const float* sp = (const float*)d_in[16];
    const float* tp = (const float*)d_in[17];
    float* out = (float*)d_out;

    cudaFuncSetAttribute(qkv_tc_kernel, cudaFuncAttributeMaxDynamicSharedMemorySize, SMEM_QKV);
    cudaFuncSetAttribute(attn_kernel, cudaFuncAttributeMaxDynamicSharedMemorySize, SMEM_ATTN);
    cudaFuncSetAttribute(projf_tc_kernel, cudaFuncAttributeMaxDynamicSharedMemorySize, SMEM_PF);

    cvt_x_kernel<<<dim3(4096, 2), 256>>>(x1, x2);
    cvt_w_kernel<<<dim3(64, 4), 256>>>(Wq, Wk, Wv, Wp);
    zero_csum_kernel<<<1, BATCH * DV>>>();
    qkv_tc_kernel<<<dim3(NTOK / 64, BATCH, 4), 256, SMEM_QKV>>>(
        bq, sq, tq, bk, sk, tk, bv, sv, tv);
    base_kernel<<<BATCH, 256>>>(Wp, bp);
    attn_kernel<<<dim3(NTOK / 64, BATCH), 256, SMEM_ATTN>>>();
    projf_tc_kernel<<<dim3(NTOK / 64, OUTC / 128, BATCH), 256, SMEM_PF>>>(sp, tp, out);
}

// round 10
// speedup vs baseline: 2.7095x; 1.0319x over previous
#include <cuda_runtime.h>
#include <cuda_bf16.h>
#include <cstdint>

#define NTOK 4096
#define BATCH 4
#define CIN 256
#define DI 128
#define DV 256
#define OUTC 256

typedef unsigned long long u64;
typedef uint32_t u32;

// ---------------- bf16 mma + ldmatrix ----------------
__device__ __forceinline__ void mmabf(float4& d, u32 a0, u32 a1, u32 a2, u32 a3,
                                      u32 b0, u32 b1) {
    asm volatile(
        "mma.sync.aligned.m16n8k16.row.col.f32.bf16.bf16.f32 "
        "{%0,%1,%2,%3}, {%4,%5,%6,%7}, {%8,%9}, {%0,%1,%2,%3};"
        : "+f"(d.x), "+f"(d.y), "+f"(d.z), "+f"(d.w)
        : "r"(a0), "r"(a1), "r"(a2), "r"(a3), "r"(b0), "r"(b1));
}
__device__ __forceinline__ void ldmx4(u32& r0, u32& r1, u32& r2, u32& r3, u32 a) {
    asm volatile("ldmatrix.sync.aligned.m8n8.x4.shared.b16 {%0,%1,%2,%3}, [%4];"
                 : "=r"(r0), "=r"(r1), "=r"(r2), "=r"(r3) : "r"(a));
}
__device__ __forceinline__ void ldmx4t(u32& r0, u32& r1, u32& r2, u32& r3, u32 a) {
    asm volatile("ldmatrix.sync.aligned.m8n8.x4.trans.shared.b16 {%0,%1,%2,%3}, [%4];"
                 : "=r"(r0), "=r"(r1), "=r"(r2), "=r"(r3) : "r"(a));
}
__device__ __forceinline__ u32 pkbf(float lo, float hi) {   // lo -> lower half
    u32 r; asm("cvt.rn.bf16x2.f32 %0, %1, %2;" : "=r"(r) : "f"(hi), "f"(lo)); return r;
}

// ---------------- cp.async helpers ----------------
__device__ __forceinline__ u32 smaddr(const void* p) {
    return (u32)__cvta_generic_to_shared(p);
}
__device__ __forceinline__ void cp16(u32 dst, const void* src) {
    asm volatile("cp.async.cg.shared.global [%0], [%1], 16;" :: "r"(dst), "l"(src));
}
#define CP_COMMIT() asm volatile("cp.async.commit_group;")
#define CP_WAIT1()  asm volatile("cp.async.wait_group 1;")
#define CP_WAIT0()  asm volatile("cp.async.wait_group 0;")

// ---------------- scratch ----------------
__device__ __nv_bfloat16 g_x1h[BATCH * CIN * NTOK];
__device__ __nv_bfloat16 g_x2h[BATCH * CIN * NTOK];
__device__ __nv_bfloat16 g_Wh[3 * 128 * 256];
__device__ __nv_bfloat16 g_Wph[256 * 256];
__device__ __nv_bfloat16 g_Qh[BATCH * NTOK * DI];    // pre-scaled by 128^-0.5
__device__ __nv_bfloat16 g_Kh[BATCH * NTOK * DI];
__device__ __nv_bfloat16 g_Vh[BATCH * NTOK * DV];    // [0:128)=v2, [128:256)=v1
__device__ __nv_bfloat16 g_corrh[BATCH * NTOK * DV]; // P·V/L (bf16)
__device__ float g_csum[BATCH * DV];
__device__ float g_base[BATCH * OUTC];               // Wp·csum + bp

// ---------------- tiny kernels ----------------
__global__ void zero_csum_kernel() { g_csum[threadIdx.x] = 0.0f; }

__global__ void cvt_x_kernel(const float* __restrict__ x1, const float* __restrict__ x2) {
    const float* src = blockIdx.y ? x2 : x1;
    __nv_bfloat16* dst = blockIdx.y ? g_x2h : g_x1h;
    int idx = (blockIdx.x * 256 + threadIdx.x) * 4;
    float4 v = *(const float4*)&src[idx];
    *(uint2*)&dst[idx] = make_uint2(pkbf(v.x, v.y), pkbf(v.z, v.w));
}

__global__ void cvt_w_kernel(const float* __restrict__ Wq, const float* __restrict__ Wk,
                             const float* __restrict__ Wv, const float* __restrict__ Wp) {
    int y = blockIdx.y;
    const float* src = (y == 0) ? Wq : (y == 1) ? Wk : (y == 2) ? Wv : Wp;
    __nv_bfloat16* dst = (y < 3) ? (g_Wh + y * 32768) : g_Wph;
    int n = (y < 3) ? 32768 : 65536;
    int idx = (blockIdx.x * 256 + threadIdx.x) * 4;
    if (idx < n) {
        float4 v = *(const float4*)&src[idx];
        *(uint2*)&dst[idx] = make_uint2(pkbf(v.x, v.y), pkbf(v.z, v.w));
    }
}

__global__ void base_kernel(const float* __restrict__ Wp, const float* __restrict__ bp) {
    __shared__ float cs[256];
    int b = blockIdx.x, o = threadIdx.x;
    cs[o] = g_csum[b * DV + o];
    __syncthreads();
    float s = bp[o];
    const float* w = Wp + (size_t)o * 256;
#pragma unroll 8
    for (int c = 0; c < 256; ++c) s += w[c] * cs[c];
    g_base[b * OUTC + o] = s;
}

// ============================================================================
// QKV projection (unchanged from round 8)
// ============================================================================
#define XS_S 72
#define WS_S 264
#define QK_OFFW 18432
#define QK_OFFC 52224
#define SMEM_QKV (52224 * 2 + 512)

__global__ __launch_bounds__(256, 2)
void qkv_tc_kernel(const float* __restrict__ bq, const float* __restrict__ sq,
                   const float* __restrict__ tq,
                   const float* __restrict__ bk, const float* __restrict__ sk,
                   const float* __restrict__ tk,
                   const float* __restrict__ bv, const float* __restrict__ sv,
                   const float* __restrict__ tv) {
    extern __shared__ uint16_t qsm[];
    float* colacc = (float*)(qsm + QK_OFFC);
    const int z = blockIdx.z, b = blockIdx.y, nbase = blockIdx.x * 64;
    const int tid = threadIdx.x, lane = tid & 31, wid = tid >> 5;
    const int wn = wid & 3, wo = wid >> 2;
    const int gq = lane >> 2, qd = lane & 3;
    const __nv_bfloat16* xh = (z == 0 || z == 3) ? g_x1h : g_x2h;
    const __nv_bfloat16* wg = g_Wh + (z < 2 ? z : 2) * 32768;
    const float* bias = (z == 0) ? bq : (z == 1) ? bk : bv;
    const float* sc = (z == 0) ? sq : (z == 1) ? sk : sv;
    const float* tr = (z == 0) ? tq : (z == 1) ? tk : tv;
    const float prescale = (z == 0) ? 0.08838834764831845f : 1.0f;
    const u32 smbase = smaddr(qsm);

    if (tid < 128) colacc[tid] = 0.0f;

    {
        const __nv_bfloat16* xg = xh + (size_t)b * CIN * NTOK + nbase;
        int seg = (tid & 7) * 8;
#pragma unroll
        for (int it = 0; it < 8; ++it) {
            int r = (tid >> 3) + 32 * it;
            cp16(smbase + (r * XS_S + seg) * 2, xg + (size_t)r * NTOK + seg);
        }
    }
    {
        int seg = (tid & 31) * 8;
#pragma unroll
        for (int it = 0; it < 16; ++it) {
            int r = (tid >> 5) + 8 * it;
            cp16(smbase + (QK_OFFW + r * WS_S + seg) * 2, wg + (size_t)r * 256 + seg);
        }
    }
    CP_COMMIT(); CP_WAIT0();
    __syncthreads();

    const u32 aX = smbase + ((((lane & 7) + ((lane >> 4) & 1) * 8)) * XS_S +
                             16 * wn + ((lane >> 3) & 1) * 8) * 2;
    const u32 aW = smbase + (QK_OFFW + (64 * wo + (lane & 7) + ((lane >> 4) & 1) * 8) * WS_S +
                             ((lane >> 3) & 1) * 8) * 2;

    float4 acc[8];
#pragma unroll
    for (int t = 0; t < 8; ++t) acc[t] = make_float4(0.f, 0.f, 0.f, 0.f);

#pragma unroll
    for (int kk = 0; kk < 16; ++kk) {
        u32 a0, a1, a2, a3;
        ldmx4t(a0, a1, a2, a3, aX + kk * 16 * XS_S * 2);
#pragma unroll
        for (int j = 0; j < 4; ++j) {
            u32 b0, b1, b2, b3;
            ldmx4(b0, b1, b2, b3, aW + (j * 16 * WS_S + kk * 16) * 2);
            mmabf(acc[2 * j], a0, a1, a2, a3, b0, b1);
            mmabf(acc[2 * j + 1], a0, a1, a2, a3, b2, b3);
        }
    }

    const int n0 = 16 * wn + gq;
    const size_t rg = (size_t)b * NTOK + nbase + n0;
#pragma unroll
    for (int t = 0; t < 8; ++t) {
        int o = 64 * wo + 8 * t + 2 * qd;
        float2 bb = *(const float2*)&bias[o];
        float2 ss = *(const float2*)&sc[o];
        float2 tt = *(const float2*)&tr[o];
        float v00 = fmaxf((acc[t].x + bb.x) * ss.x + tt.x, 0.f) * prescale;
        float v01 = fmaxf((acc[t].y + bb.y) * ss.y + tt.y, 0.f) * prescale;
        float v10 = fmaxf((acc[t].z + bb.x) * ss.x + tt.x, 0.f) * prescale;
        float v11 = fmaxf((acc[t].w + bb.y) * ss.y + tt.y, 0.f) * prescale;
        if (z == 0) {
            *(u32*)&g_Qh[rg * DI + o] = pkbf(v00, v01);
            *(u32*)&g_Qh[(rg + 8) * DI + o] = pkbf(v10, v11);
        } else if (z == 1) {
            *(u32*)&g_Kh[rg * DI + o] = pkbf(v00, v01);
            *(u32*)&g_Kh[(rg + 8) * DI + o] = pkbf(v10, v11);
        } else {
            int oc = o + (z == 3 ? 128 : 0);
            *(u32*)&g_Vh[rg * DV + oc] = pkbf(v00, v01);
            *(u32*)&g_Vh[(rg + 8) * DV + oc] = pkbf(v10, v11);
            atomicAdd(&colacc[o], v00 + v10);
            atomicAdd(&colacc[o + 1], v01 + v11);
        }
    }
    if (z >= 2) {
        __syncthreads();
        if (tid < 128) {
            int ofs = (z == 3) ? 128 : 0;
            atomicAdd(&g_csum[b * DV + ofs + tid], colacc[tid]);
        }
    }
}

// ============================================================================
// bf16 flash attention, BR=128 fat-row warps. 8 warps.
// S phase: 4(row x32) x 2(col x32); PV phase: 2(row x64) x 4(col x64).
// One cp.async group per 64-token tile {K,V}, two in flight.
// ============================================================================
#define QK_S 136
#define V_S  264
#define P_S  72
#define OFF_K 17408
#define OFF_V 34816
#define OFF_P 68608
#define OFF_RED 77824
#define SMEM_ATTN (OFF_RED * 2 + 768 * 4)

__global__ __launch_bounds__(256, 1)
void attn_kernel() {
    extern __shared__ uint16_t smh[];
    float* red = (float*)(smh + OFF_RED);  // [0:256) mx, [256:512) sums, [512:640) corr, [640:768) L

    const int b = blockIdx.y;
    const int nbase = blockIdx.x * 128;
    const int tid = threadIdx.x;
    const int wid = tid >> 5, lane = tid & 31;
    const int wr = wid >> 1, wc = wid & 1;
    const int wp = wid >> 2, wq = wid & 3;
    const int gq = lane >> 2, qd = lane & 3;

    const int rQ = tid >> 4, cQ = (tid & 15) * 8;
    const int rV = tid >> 5, cV = (tid & 31) * 8;
    const __nv_bfloat16* Qg = g_Qh + ((size_t)b * NTOK + nbase) * DI;
    const __nv_bfloat16* Kg0 = g_Kh + (size_t)b * NTOK * DI;
    const __nv_bfloat16* Vg0 = g_Vh + (size_t)b * NTOK * DV;
    const u32 smbase = smaddr(smh);

    // prologue: group0 = {Q, K(0), V(0)}; group1 = {K(1), V(1)}
#pragma unroll
    for (int it = 0; it < 8; ++it) {
        int r = rQ + 16 * it;
        cp16(smbase + (r * QK_S + cQ) * 2, Qg + (size_t)r * DI + cQ);
    }
#pragma unroll
    for (int it = 0; it < 4; ++it) {
        int r = rQ + 16 * it;
        cp16(smbase + (OFF_K + r * QK_S + cQ) * 2, Kg0 + (size_t)r * DI + cQ);
    }
#pragma unroll
    for (int it = 0; it < 8; ++it) {
        int r = rV + 8 * it;
        cp16(smbase + (OFF_V + r * V_S + cV) * 2, Vg0 + (size_t)r * DV + cV);
    }
    CP_COMMIT();
#pragma unroll
    for (int it = 0; it < 4; ++it) {
        int r = rQ + 16 * it;
        cp16(smbase + (OFF_K + 8704 + r * QK_S + cQ) * 2, Kg0 + (size_t)(64 + r) * DI + cQ);
    }
#pragma unroll
    for (int it = 0; it < 8; ++it) {
        int r = rV + 8 * it;
        cp16(smbase + (OFF_V + 16896 + r * V_S + cV) * 2, Vg0 + (size_t)(64 + r) * DV + cV);
    }
    CP_COMMIT();

    const u32 aQ0 = smbase + ((32 * wr + (lane & 15)) * QK_S + (lane >> 4) * 8) * 2;
    const u32 aQ1 = aQ0 + 16 * QK_S * 2;
    const u32 aKoff = ((32 * wc + (lane & 7) + (lane >> 4) * 8) * QK_S +
                      ((lane >> 3) & 1) * 8) * 2;
    const u32 aPb = smbase + (OFF_P + (64 * wp + (lane & 15)) * P_S + (lane >> 4) * 8) * 2;
    const u32 aVoff = (((lane & 7) + ((lane >> 3) & 1) * 8) * V_S +
                       64 * wq + (lane >> 4) * 8) * 2;

    float M[4], L[4];   // [2f+h]: row 32wr+16f+gq+8h
#pragma unroll
    for (int i = 0; i < 4; ++i) { M[i] = -1e30f; L[i] = 0.0f; }
    float4 acc[4][8];   // [rf: rows 64wp+16rf+gq(+8)][t: cols 64wq+8t+2qd]
#pragma unroll
    for (int rf = 0; rf < 4; ++rf)
#pragma unroll
        for (int t = 0; t < 8; ++t) acc[rf][t] = make_float4(0.f, 0.f, 0.f, 0.f);

    for (int tl = 0; tl < 64; ++tl) {
        const bool more = (tl + 2) < 64;
        CP_WAIT1();
        __syncthreads();   // (A) tile tl resident for all threads
        const u32 kbuf = smbase + (OFF_K + (tl & 1) * 8704) * 2;
        const u32 vbuf = smbase + (OFF_V + (tl & 1) * 16896) * 2;

        // ---- S = Q K^T : 2 row-frags x 4 col-tiles ----
        float4 S[2][4];
#pragma unroll
        for (int f = 0; f < 2; ++f)
#pragma unroll
            for (int t = 0; t < 4; ++t) S[f][t] = make_float4(0.f, 0.f, 0.f, 0.f);
        const u32 aK = kbuf + aKoff;
        const u32 aK2 = aK + 16 * QK_S * 2;
#pragma unroll
        for (int kk = 0; kk < 8; ++kk) {
            u32 q00, q01, q02, q03, q10, q11, q12, q13;
            ldmx4(q00, q01, q02, q03, aQ0 + kk * 32);
            ldmx4(q10, q11, q12, q13, aQ1 + kk * 32);
            u32 b00, b01, b10, b11, b20, b21, b30, b31;
            ldmx4(b00, b01, b10, b11, aK + kk * 32);
            ldmx4(b20, b21, b30, b31, aK2 + kk * 32);
            mmabf(S[0][0], q00, q01, q02, q03, b00, b01);
            mmabf(S[0][1], q00, q01, q02, q03, b10, b11);
            mmabf(S[0][2], q00, q01, q02, q03, b20, b21);
            mmabf(S[0][3], q00, q01, q02, q03, b30, b31);
            mmabf(S[1][0], q10, q11, q12, q13, b00, b01);
            mmabf(S[1][1], q10, q11, q12, q13, b10, b11);
            mmabf(S[1][2], q10, q11, q12, q13, b20, b21);
            mmabf(S[1][3], q10, q11, q12, q13, b30, b31);
        }

        // ---- row max partials ----
#pragma unroll
        for (int f = 0; f < 2; ++f) {
            float mx0 = fmaxf(fmaxf(S[f][0].x, S[f][0].y), fmaxf(S[f][1].x, S[f][1].y));
            mx0 = fmaxf(mx0, fmaxf(fmaxf(S[f][2].x, S[f][2].y), fmaxf(S[f][3].x, S[f][3].y)));
            float mx1 = fmaxf(fmaxf(S[f][0].z, S[f][0].w), fmaxf(S[f][1].z, S[f][1].w));
            mx1 = fmaxf(mx1, fmaxf(fmaxf(S[f][2].z, S[f][2].w), fmaxf(S[f][3].z, S[f][3].w)));
            mx0 = fmaxf(mx0, __shfl_xor_sync(0xffffffffu, mx0, 1));
            mx0 = fmaxf(mx0, __shfl_xor_sync(0xffffffffu, mx0, 2));
            mx1 = fmaxf(mx1, __shfl_xor_sync(0xffffffffu, mx1, 1));
            mx1 = fmaxf(mx1, __shfl_xor_sync(0xffffffffu, mx1, 2));
            if (qd == 0) {
                int r0 = 32 * wr + 16 * f + gq;
                red[wc * 128 + r0] = mx0;
                red[wc * 128 + r0 + 8] = mx1;
            }
        }
        __syncthreads();   // (B)

        // ---- newM, corr, exp, P store, sum partials ----
        float nM[4], corr[4];
#pragma unroll
        for (int f = 0; f < 2; ++f) {
            int r0 = 32 * wr + 16 * f + gq;
            float m0 = fmaxf(M[2 * f], fmaxf(red[r0], red[128 + r0]));
            float m1 = fmaxf(M[2 * f + 1], fmaxf(red[r0 + 8], red[128 + r0 + 8]));
            corr[2 * f] = __expf(M[2 * f] - m0);
            corr[2 * f + 1] = __expf(M[2 * f + 1] - m1);
            nM[2 * f] = m0; nM[2 * f + 1] = m1;
            if (wc == 0 && qd == 0) {
                red[512 + r0] = corr[2 * f];
                red[512 + r0 + 8] = corr[2 * f + 1];
            }
            float s0 = 0.0f, s1 = 0.0f;
#pragma unroll
            for (int t = 0; t < 4; ++t) {
                S[f][t].x = __expf(S[f][t].x - m0);
                S[f][t].y = __expf(S[f][t].y - m0);
                S[f][t].z = __expf(S[f][t].z - m1);
                S[f][t].w = __expf(S[f][t].w - m1);
                s0 += S[f][t].x + S[f][t].y;
                s1 += S[f][t].z + S[f][t].w;
                int col = 32 * wc + 8 * t + 2 * qd;
                *(u32*)(smh + OFF_P + r0 * P_S + col) = pkbf(S[f][t].x, S[f][t].y);
                *(u32*)(smh + OFF_P + (r0 + 8) * P_S + col) = pkbf(S[f][t].z, S[f][t].w);
            }
            s0 += __shfl_xor_sync(0xffffffffu, s0, 1);
            s0 += __shfl_xor_sync(0xffffffffu, s0, 2);
            s1 += __shfl_xor_sync(0xffffffffu, s1, 1);
            s1 += __shfl_xor_sync(0xffffffffu, s1, 2);
            if (qd == 0) {
                red[256 + wc * 128 + r0] = s0;
                red[256 + wc * 128 + r0 + 8] = s1;
            }
        }
        __syncthreads();   // (C)

#pragma unroll
        for (int f = 0; f < 2; ++f) {
            int r0 = 32 * wr + 16 * f + gq;
            L[2 * f] = L[2 * f] * corr[2 * f] + red[256 + r0] + red[384 + r0];
            L[2 * f + 1] = L[2 * f + 1] * corr[2 * f + 1] +
                           red[256 + r0 + 8] + red[384 + r0 + 8];
            M[2 * f] = nM[2 * f]; M[2 * f + 1] = nM[2 * f + 1];
        }

        // ---- scale acc by corr (PV rows) ----
#pragma unroll
        for (int rf = 0; rf < 4; ++rf) {
            float ca = red[512 + 64 * wp + 16 * rf + gq];
            float cb = red[512 + 64 * wp + 16 * rf + gq + 8];
#pragma unroll
            for (int t = 0; t < 8; ++t) {
                acc[rf][t].x *= ca; acc[rf][t].y *= ca;
                acc[rf][t].z *= cb; acc[rf][t].w *= cb;
            }
        }

        // ---- O += P V : 4 row-frags x 8 col-tiles, k=64 ----
#pragma unroll
        for (int kk = 0; kk < 4; ++kk) {
            u32 pa[4][4];
#pragma unroll
            for (int rf = 0; rf < 4; ++rf)
                ldmx4(pa[rf][0], pa[rf][1], pa[rf][2], pa[rf][3],
                      aPb + rf * (16 * P_S * 2) + kk * 32);
            u32 vrow = vbuf + aVoff + kk * (16 * V_S * 2);
#pragma unroll
            for (int p = 0; p < 4; ++p) {
                u32 b0, b1, b2, b3;
                ldmx4t(b0, b1, b2, b3, vrow + p * 32);
#pragma unroll
                for (int rf = 0; rf < 4; ++rf) {
                    mmabf(acc[rf][2 * p], pa[rf][0], pa[rf][1], pa[rf][2], pa[rf][3], b0, b1);
                    mmabf(acc[rf][2 * p + 1], pa[rf][0], pa[rf][1], pa[rf][2], pa[rf][3], b2, b3);
                }
            }
        }
        __syncthreads();   // (D) K/V/P consumers done

        if (more) {
            const __nv_bfloat16* Kg = Kg0 + (size_t)(tl + 2) * 64 * DI;
            const __nv_bfloat16* Vg = Vg0 + (size_t)(tl + 2) * 64 * DV;
            u32 kd = smbase + (OFF_K + (tl & 1) * 8704) * 2;
            u32 vd = smbase + (OFF_V + (tl & 1) * 16896) * 2;
#pragma unroll
            for (int it = 0; it < 4; ++it) {
                int r = rQ + 16 * it;
                cp16(kd + (r * QK_S + cQ) * 2, Kg + (size_t)r * DI + cQ);
            }
#pragma unroll
            for (int it = 0; it < 8; ++it) {
                int r = rV + 8 * it;
                cp16(vd + (r * V_S + cV) * 2, Vg + (size_t)r * DV + cV);
            }
            CP_COMMIT();
        }
    }

    // ---- epilogue: corr_out = acc / L (bf16) ----
    if (wc == 0 && qd == 0) {
#pragma unroll
        for (int f = 0; f < 2; ++f) {
            int r0 = 32 * wr + 16 * f + gq;
            red[640 + r0] = L[2 * f];
            red[640 + r0 + 8] = L[2 * f + 1];
        }
    }
    __syncthreads();
    __nv_bfloat16* og = g_corrh + ((size_t)b * NTOK + nbase) * DV;
#pragma unroll
    for (int rf = 0; rf < 4; ++rf) {
        int ra = 64 * wp + 16 * rf + gq;
        float ia = 1.0f / red[640 + ra];
        float ib = 1.0f / red[640 + ra + 8];
#pragma unroll
        for (int t = 0; t < 8; ++t) {
            int col = 64 * wq + 8 * t + 2 * qd;
            *(u32*)&og[(size_t)ra * DV + col] = pkbf(acc[rf][t].x * ia, acc[rf][t].y * ia);
            *(u32*)&og[(size_t)(ra + 8) * DV + col] = pkbf(acc[rf][t].z * ib, acc[rf][t].w * ib);
        }
    }
}

// ============================================================================
// Output projection (unchanged from round 8)
// ============================================================================
#define PF_OFFW 16896
#define SMEM_PF ((16896 + 33792) * 2)

__global__ __launch_bounds__(256, 2)
void projf_tc_kernel(const float* __restrict__ sp, const float* __restrict__ tp,
                     float* __restrict__ out) {
    extern __shared__ uint16_t psm[];
    const int b = blockIdx.z, obase = blockIdx.y * 128, nbase = blockIdx.x * 64;
    const int tid = threadIdx.x, lane = tid & 31, wid = tid >> 5;
    const int gq = lane >> 2, qd = lane & 3;
    const u32 smbase = smaddr(psm);

    {
        const __nv_bfloat16* cg = g_corrh + ((size_t)b * NTOK + nbase) * DV;
        int seg = (tid & 31) * 8;
#pragma unroll
        for (int it = 0; it < 8; ++it) {
            int r = (tid >> 5) + 8 * it;
            cp16(smbase + (r * WS_S + seg) * 2, cg + (size_t)r * DV + seg);
        }
        const __nv_bfloat16* wg = g_Wph + (size_t)obase * 256;
#pragma unroll
        for (int it = 0; it < 16; ++it) {
            int r = (tid >> 5) + 8 * it;
            cp16(smbase + (PF_OFFW + r * WS_S + seg) * 2, wg + (size_t)r * 256 + seg);
        }
    }
    CP_COMMIT(); CP_WAIT0();
    __syncthreads();

    const u32 aA = smbase + (PF_OFFW + (16 * wid + (lane & 15)) * WS_S + (lane >> 4) * 8) * 2;
    const u32 aB = smbase + (((lane & 7) + ((lane >> 4) & 1) * 8) * WS_S +
                             ((lane >> 3) & 1) * 8) * 2;

    float4 acc[8];
#pragma unroll
    for (int t = 0; t < 8; ++t) acc[t] = make_float4(0.f, 0.f, 0.f, 0.f);

#pragma unroll
    for (int kk = 0; kk < 16; ++kk) {
        u32 a0, a1, a2, a3;
        ldmx4(a0, a1, a2, a3, aA + kk * 16 * 2);
#pragma unroll
        for (int j = 0; j < 4; ++j) {
            u32 b0, b1, b2, b3;
            ldmx4(b0, b1, b2, b3, aB + (j * 16 * WS_S + kk * 16) * 2);
            mmabf(acc[2 * j], a0, a1, a2, a3, b0, b1);
            mmabf(acc[2 * j + 1], a0, a1, a2, a3, b2, b3);
        }
    }

    const int o0 = obase + 16 * wid + gq;
    float bs0 = g_base[b * OUTC + o0], bs1 = g_base[b * OUTC + o0 + 8];
    float sp0 = sp[o0], sp1 = sp[o0 + 8], tp0 = tp[o0], tp1 = tp[o0 + 8];
    float* og0 = out + ((size_t)b * OUTC + o0) * NTOK + nbase;
    float* og1 = og0 + (size_t)8 * NTOK;
#pragma unroll
    for (int t = 0; t < 8; ++t) {
        int n = 8 * t + 2 * qd;
        float2 r0, r1;
        r0.x = fmaxf((bs0 - acc[t].x) * sp0 + tp0, 0.f);
        r0.y = fmaxf((bs0 - acc[t].y) * sp0 + tp0, 0.f);
        r1.x = fmaxf((bs1 - acc[t].z) * sp1 + tp1, 0.f);
        r1.y = fmaxf((bs1 - acc[t].w) * sp1 + tp1, 0.f);
        *(float2*)&og0[n] = r0;
        *(float2*)&og1[n] = r1;
    }
}

extern "C" void kernel_launch(void* const* d_in, const int* in_sizes, int n_in,
                              void* d_out, int out_size) {
    const float* x1 = (const float*)d_in[0];
    const float* x2 = (const float*)d_in[1];
    const float* Wq = (const float*)d_in[2];
    const float* bq = (const float*)d_in[3];
    const float* sq = (const float*)d_in[4];
    const float* tq = (const float*)d_in[5];
    const float* Wk = (const float*)d_in[6];
    const float* bk = (const float*)d_in[7];
    const float* sk = (const float*)d_in[8];
    const float* tk = (const float*)d_in[9];
    const float* Wv = (const float*)d_in[10];
    const float* bv = (const float*)d_in[11];
    const float* sv = (const float*)d_in[12];
    const float* tv = (const float*)d_in[13];
    const float* Wp = (const float*)d_in[14];
    const float* bp = (const float*)d_in[15];
    const float* sp = (const float*)d_in[16];
    const float* tp = (const float*)d_in[17];
    float* out = (float*)d_out;

    cudaFuncSetAttribute(qkv_tc_kernel, cudaFuncAttributeMaxDynamicSharedMemorySize, SMEM_QKV);
    cudaFuncSetAttribute(attn_kernel, cudaFuncAttributeMaxDynamicSharedMemorySize, SMEM_ATTN);
    cudaFuncSetAttribute(projf_tc_kernel, cudaFuncAttributeMaxDynamicSharedMemorySize, SMEM_PF);

    cvt_x_kernel<<<dim3(4096, 2), 256>>>(x1, x2);
    cvt_w_kernel<<<dim3(64, 4), 256>>>(Wq, Wk, Wv, Wp);
    zero_csum_kernel<<<1, BATCH * DV>>>();
    qkv_tc_kernel<<<dim3(NTOK / 64, BATCH, 4), 256, SMEM_QKV>>>(
        bq, sq, tq, bk, sk, tk, bv, sv, tv);
    base_kernel<<<BATCH, 256>>>(Wp, bp);
    attn_kernel<<<dim3(NTOK / 128, BATCH), 256, SMEM_ATTN>>>();
    projf_tc_kernel<<<dim3(NTOK / 64, OUTC / 128, BATCH), 256, SMEM_PF>>>(sp, tp, out);
}

// round 11
// speedup vs baseline: 3.0347x; 1.1200x over previous
#include <cuda_runtime.h>
#include <cuda_bf16.h>
#include <cstdint>

#define NTOK 4096
#define BATCH 4
#define CIN 256
#define DI 128
#define DV 256
#define OUTC 256

typedef unsigned long long u64;
typedef uint32_t u32;

// ---------------- bf16 mma + ldmatrix ----------------
__device__ __forceinline__ void mmabf(float4& d, u32 a0, u32 a1, u32 a2, u32 a3,
                                      u32 b0, u32 b1) {
    asm volatile(
        "mma.sync.aligned.m16n8k16.row.col.f32.bf16.bf16.f32 "
        "{%0,%1,%2,%3}, {%4,%5,%6,%7}, {%8,%9}, {%0,%1,%2,%3};"
        : "+f"(d.x), "+f"(d.y), "+f"(d.z), "+f"(d.w)
        : "r"(a0), "r"(a1), "r"(a2), "r"(a3), "r"(b0), "r"(b1));
}
__device__ __forceinline__ void ldmx4(u32& r0, u32& r1, u32& r2, u32& r3, u32 a) {
    asm volatile("ldmatrix.sync.aligned.m8n8.x4.shared.b16 {%0,%1,%2,%3}, [%4];"
                 : "=r"(r0), "=r"(r1), "=r"(r2), "=r"(r3) : "r"(a));
}
__device__ __forceinline__ void ldmx4t(u32& r0, u32& r1, u32& r2, u32& r3, u32 a) {
    asm volatile("ldmatrix.sync.aligned.m8n8.x4.trans.shared.b16 {%0,%1,%2,%3}, [%4];"
                 : "=r"(r0), "=r"(r1), "=r"(r2), "=r"(r3) : "r"(a));
}
__device__ __forceinline__ u32 pkbf(float lo, float hi) {
    u32 r; asm("cvt.rn.bf16x2.f32 %0, %1, %2;" : "=r"(r) : "f"(hi), "f"(lo)); return r;
}
__device__ __forceinline__ float ex2f(float x) {
    float r; asm("ex2.approx.f32 %0, %1;" : "=f"(r) : "f"(x)); return r;
}

// ---------------- cp.async helpers ----------------
__device__ __forceinline__ u32 smaddr(const void* p) {
    return (u32)__cvta_generic_to_shared(p);
}
__device__ __forceinline__ void cp16(u32 dst, const void* src) {
    asm volatile("cp.async.cg.shared.global [%0], [%1], 16;" :: "r"(dst), "l"(src));
}
#define CP_COMMIT() asm volatile("cp.async.commit_group;")
#define CP_WAIT1()  asm volatile("cp.async.wait_group 1;")
#define CP_WAIT0()  asm volatile("cp.async.wait_group 0;")

// ---------------- scratch ----------------
__device__ __nv_bfloat16 g_x1h[BATCH * CIN * NTOK];
__device__ __nv_bfloat16 g_x2h[BATCH * CIN * NTOK];
__device__ __nv_bfloat16 g_Wh[3 * 128 * 256];
__device__ __nv_bfloat16 g_Wph[256 * 256];
__device__ __nv_bfloat16 g_Qh[BATCH * NTOK * DI];    // pre-scaled by 128^-0.5 * log2(e)
__device__ __nv_bfloat16 g_Kh[BATCH * NTOK * DI];
__device__ __nv_bfloat16 g_Vh[BATCH * NTOK * DV];    // [0:128)=v2, [128:256)=v1
__device__ __nv_bfloat16 g_corrh[BATCH * NTOK * DV]; // P·V/L (bf16)
__device__ float g_csum[BATCH * DV];
__device__ float g_base[BATCH * OUTC];

// ---------------- tiny kernels ----------------
__global__ void zero_csum_kernel() { g_csum[threadIdx.x] = 0.0f; }

__global__ void cvt_x_kernel(const float* __restrict__ x1, const float* __restrict__ x2) {
    const float* src = blockIdx.y ? x2 : x1;
    __nv_bfloat16* dst = blockIdx.y ? g_x2h : g_x1h;
    int idx = (blockIdx.x * 256 + threadIdx.x) * 4;
    float4 v = *(const float4*)&src[idx];
    *(uint2*)&dst[idx] = make_uint2(pkbf(v.x, v.y), pkbf(v.z, v.w));
}

__global__ void cvt_w_kernel(const float* __restrict__ Wq, const float* __restrict__ Wk,
                             const float* __restrict__ Wv, const float* __restrict__ Wp) {
    int y = blockIdx.y;
    const float* src = (y == 0) ? Wq : (y == 1) ? Wk : (y == 2) ? Wv : Wp;
    __nv_bfloat16* dst = (y < 3) ? (g_Wh + y * 32768) : g_Wph;
    int n = (y < 3) ? 32768 : 65536;
    int idx = (blockIdx.x * 256 + threadIdx.x) * 4;
    if (idx < n) {
        float4 v = *(const float4*)&src[idx];
        *(uint2*)&dst[idx] = make_uint2(pkbf(v.x, v.y), pkbf(v.z, v.w));
    }
}

__global__ void base_kernel(const float* __restrict__ Wp, const float* __restrict__ bp) {
    __shared__ float cs[256];
    int b = blockIdx.x, o = threadIdx.x;
    cs[o] = g_csum[b * DV + o];
    __syncthreads();
    float s = bp[o];
    const float* w = Wp + (size_t)o * 256;
#pragma unroll 8
    for (int c = 0; c < 256; ++c) s += w[c] * cs[c];
    g_base[b * OUTC + o] = s;
}

// ============================================================================
// QKV projection, bf16 TC, k-split software pipeline (2 halves).
// ============================================================================
#define XS_S 72
#define WS_S 264
#define QK_OFFW 18432
#define QK_OFFC 52224
#define SMEM_QKV (52224 * 2 + 512)

__global__ __launch_bounds__(256, 2)
void qkv_tc_kernel(const float* __restrict__ bq, const float* __restrict__ sq,
                   const float* __restrict__ tq,
                   const float* __restrict__ bk, const float* __restrict__ sk,
                   const float* __restrict__ tk,
                   const float* __restrict__ bv, const float* __restrict__ sv,
                   const float* __restrict__ tv) {
    extern __shared__ uint16_t qsm[];
    float* colacc = (float*)(qsm + QK_OFFC);
    const int z = blockIdx.z, b = blockIdx.y, nbase = blockIdx.x * 64;
    const int tid = threadIdx.x, lane = tid & 31, wid = tid >> 5;
    const int wn = wid & 3, wo = wid >> 2;
    const int gq = lane >> 2, qd = lane & 3;
    const __nv_bfloat16* xh = (z == 0 || z == 3) ? g_x1h : g_x2h;
    const __nv_bfloat16* wg = g_Wh + (z < 2 ? z : 2) * 32768;
    const float* bias = (z == 0) ? bq : (z == 1) ? bk : bv;
    const float* sc = (z == 0) ? sq : (z == 1) ? sk : sv;
    const float* tr = (z == 0) ? tq : (z == 1) ? tk : tv;
    // Q carries 128^-0.5 * log2(e) so softmax runs in exp2 domain
    const float prescale = (z == 0) ? 0.12751743f : 1.0f;
    const u32 smbase = smaddr(qsm);

    if (tid < 128) colacc[tid] = 0.0f;

    const __nv_bfloat16* xg = xh + (size_t)b * CIN * NTOK + nbase;
    const int segX = (tid & 7) * 8;
    const int segW = (tid & 15) * 8;
    // group0: X rows [0,128), W cols [0,128)
#pragma unroll
    for (int it = 0; it < 4; ++it) {
        int r = (tid >> 3) + 32 * it;
        cp16(smbase + (r * XS_S + segX) * 2, xg + (size_t)r * NTOK + segX);
    }
#pragma unroll
    for (int it = 0; it < 8; ++it) {
        int r = (tid >> 4) + 16 * it;
        cp16(smbase + (QK_OFFW + r * WS_S + segW) * 2, wg + (size_t)r * 256 + segW);
    }
    CP_COMMIT();
    // group1: X rows [128,256), W cols [128,256)
#pragma unroll
    for (int it = 4; it < 8; ++it) {
        int r = (tid >> 3) + 32 * it;
        cp16(smbase + (r * XS_S + segX) * 2, xg + (size_t)r * NTOK + segX);
    }
#pragma unroll
    for (int it = 0; it < 8; ++it) {
        int r = (tid >> 4) + 16 * it;
        cp16(smbase + (QK_OFFW + r * WS_S + segW + 128) * 2, wg + (size_t)r * 256 + segW + 128);
    }
    CP_COMMIT();

    const u32 aX = smbase + ((((lane & 7) + ((lane >> 4) & 1) * 8)) * XS_S +
                             16 * wn + ((lane >> 3) & 1) * 8) * 2;
    const u32 aW = smbase + (QK_OFFW + (64 * wo + (lane & 7) + ((lane >> 4) & 1) * 8) * WS_S +
                             ((lane >> 3) & 1) * 8) * 2;

    float4 acc[8];
#pragma unroll
    for (int t = 0; t < 8; ++t) acc[t] = make_float4(0.f, 0.f, 0.f, 0.f);

    CP_WAIT1();
    __syncthreads();
#pragma unroll
    for (int kk = 0; kk < 8; ++kk) {
        u32 a0, a1, a2, a3;
        ldmx4t(a0, a1, a2, a3, aX + kk * 16 * XS_S * 2);
#pragma unroll
        for (int j = 0; j < 4; ++j) {
            u32 b0, b1, b2, b3;
            ldmx4(b0, b1, b2, b3, aW + (j * 16 * WS_S + kk * 16) * 2);
            mmabf(acc[2 * j], a0, a1, a2, a3, b0, b1);
            mmabf(acc[2 * j + 1], a0, a1, a2, a3, b2, b3);
        }
    }
    CP_WAIT0();
    __syncthreads();
#pragma unroll
    for (int kk = 8; kk < 16; ++kk) {
        u32 a0, a1, a2, a3;
        ldmx4t(a0, a1, a2, a3, aX + kk * 16 * XS_S * 2);
#pragma unroll
        for (int j = 0; j < 4; ++j) {
            u32 b0, b1, b2, b3;
            ldmx4(b0, b1, b2, b3, aW + (j * 16 * WS_S + kk * 16) * 2);
            mmabf(acc[2 * j], a0, a1, a2, a3, b0, b1);
            mmabf(acc[2 * j + 1], a0, a1, a2, a3, b2, b3);
        }
    }

    const int n0 = 16 * wn + gq;
    const size_t rg = (size_t)b * NTOK + nbase + n0;
#pragma unroll
    for (int t = 0; t < 8; ++t) {
        int o = 64 * wo + 8 * t + 2 * qd;
        float2 bb = *(const float2*)&bias[o];
        float2 ss = *(const float2*)&sc[o];
        float2 tt = *(const float2*)&tr[o];
        float v00 = fmaxf((acc[t].x + bb.x) * ss.x + tt.x, 0.f) * prescale;
        float v01 = fmaxf((acc[t].y + bb.y) * ss.y + tt.y, 0.f) * prescale;
        float v10 = fmaxf((acc[t].z + bb.x) * ss.x + tt.x, 0.f) * prescale;
        float v11 = fmaxf((acc[t].w + bb.y) * ss.y + tt.y, 0.f) * prescale;
        if (z == 0) {
            *(u32*)&g_Qh[rg * DI + o] = pkbf(v00, v01);
            *(u32*)&g_Qh[(rg + 8) * DI + o] = pkbf(v10, v11);
        } else if (z == 1) {
            *(u32*)&g_Kh[rg * DI + o] = pkbf(v00, v01);
            *(u32*)&g_Kh[(rg + 8) * DI + o] = pkbf(v10, v11);
        } else {
            int oc = o + (z == 3 ? 128 : 0);
            *(u32*)&g_Vh[rg * DV + oc] = pkbf(v00, v01);
            *(u32*)&g_Vh[(rg + 8) * DV + oc] = pkbf(v10, v11);
            atomicAdd(&colacc[o], v00 + v10);
            atomicAdd(&colacc[o + 1], v01 + v11);
        }
    }
    if (z >= 2) {
        __syncthreads();
        if (tid < 128) {
            int ofs = (z == 3) ? 128 : 0;
            atomicAdd(&g_csum[b * DV + ofs + tid], colacc[tid]);
        }
    }
}

// ============================================================================
// bf16 flash attention, NO-MAX softmax: P = exp2(S - 8), L summed in registers,
// reduced once in epilogue. BR=128, 8 warps; S: 4x2, PV: 2x4. 3 syncs/tile.
// ============================================================================
#define QK_S 136
#define V_S  264
#define P_S  72
#define OFF_K 17408
#define OFF_V 34816
#define OFF_P 68608
#define OFF_RED 77824
#define SMEM_ATTN (OFF_RED * 2 + 768 * 4)
#define SHIFT 8.0f

__global__ __launch_bounds__(256, 1)
void attn_kernel() {
    extern __shared__ uint16_t smh[];
    float* red = (float*)(smh + OFF_RED);   // [0:256) L partials

    const int b = blockIdx.y;
    const int nbase = blockIdx.x * 128;
    const int tid = threadIdx.x;
    const int wid = tid >> 5, lane = tid & 31;
    const int wr = wid >> 1, wc = wid & 1;
    const int wp = wid >> 2, wq = wid & 3;
    const int gq = lane >> 2, qd = lane & 3;

    const int rQ = tid >> 4, cQ = (tid & 15) * 8;
    const int rV = tid >> 5, cV = (tid & 31) * 8;
    const __nv_bfloat16* Qg = g_Qh + ((size_t)b * NTOK + nbase) * DI;
    const __nv_bfloat16* Kg0 = g_Kh + (size_t)b * NTOK * DI;
    const __nv_bfloat16* Vg0 = g_Vh + (size_t)b * NTOK * DV;
    const u32 smbase = smaddr(smh);

#pragma unroll
    for (int it = 0; it < 8; ++it) {
        int r = rQ + 16 * it;
        cp16(smbase + (r * QK_S + cQ) * 2, Qg + (size_t)r * DI + cQ);
    }
#pragma unroll
    for (int it = 0; it < 4; ++it) {
        int r = rQ + 16 * it;
        cp16(smbase + (OFF_K + r * QK_S + cQ) * 2, Kg0 + (size_t)r * DI + cQ);
    }
#pragma unroll
    for (int it = 0; it < 8; ++it) {
        int r = rV + 8 * it;
        cp16(smbase + (OFF_V + r * V_S + cV) * 2, Vg0 + (size_t)r * DV + cV);
    }
    CP_COMMIT();
#pragma unroll
    for (int it = 0; it < 4; ++it) {
        int r = rQ + 16 * it;
        cp16(smbase + (OFF_K + 8704 + r * QK_S + cQ) * 2, Kg0 + (size_t)(64 + r) * DI + cQ);
    }
#pragma unroll
    for (int it = 0; it < 8; ++it) {
        int r = rV + 8 * it;
        cp16(smbase + (OFF_V + 16896 + r * V_S + cV) * 2, Vg0 + (size_t)(64 + r) * DV + cV);
    }
    CP_COMMIT();

    const u32 aQ0 = smbase + ((32 * wr + (lane & 15)) * QK_S + (lane >> 4) * 8) * 2;
    const u32 aQ1 = aQ0 + 16 * QK_S * 2;
    const u32 aKoff = ((32 * wc + (lane & 7) + (lane >> 4) * 8) * QK_S +
                      ((lane >> 3) & 1) * 8) * 2;
    const u32 aPb = smbase + (OFF_P + (64 * wp + (lane & 15)) * P_S + (lane >> 4) * 8) * 2;
    const u32 aVoff = (((lane & 7) + ((lane >> 3) & 1) * 8) * V_S +
                       64 * wq + (lane >> 4) * 8) * 2;

    float Lp[4] = {0.f, 0.f, 0.f, 0.f};   // [2f+h]: row 32wr+16f+gq+8h
    float4 acc[4][8];
#pragma unroll
    for (int rf = 0; rf < 4; ++rf)
#pragma unroll
        for (int t = 0; t < 8; ++t) acc[rf][t] = make_float4(0.f, 0.f, 0.f, 0.f);

    for (int tl = 0; tl < 64; ++tl) {
        const bool more = (tl + 2) < 64;
        CP_WAIT1();
        __syncthreads();   // (A)
        const u32 kbuf = smbase + (OFF_K + (tl & 1) * 8704) * 2;
        const u32 vbuf = smbase + (OFF_V + (tl & 1) * 16896) * 2;

        // ---- S = Q K^T ----
        float4 S[2][4];
#pragma unroll
        for (int f = 0; f < 2; ++f)
#pragma unroll
            for (int t = 0; t < 4; ++t) S[f][t] = make_float4(0.f, 0.f, 0.f, 0.f);
        const u32 aK = kbuf + aKoff;
        const u32 aK2 = aK + 16 * QK_S * 2;
#pragma unroll
        for (int kk = 0; kk < 8; ++kk) {
            u32 q00, q01, q02, q03, q10, q11, q12, q13;
            ldmx4(q00, q01, q02, q03, aQ0 + kk * 32);
            ldmx4(q10, q11, q12, q13, aQ1 + kk * 32);
            u32 b00, b01, b10, b11, b20, b21, b30, b31;
            ldmx4(b00, b01, b10, b11, aK + kk * 32);
            ldmx4(b20, b21, b30, b31, aK2 + kk * 32);
            mmabf(S[0][0], q00, q01, q02, q03, b00, b01);
            mmabf(S[0][1], q00, q01, q02, q03, b10, b11);
            mmabf(S[0][2], q00, q01, q02, q03, b20, b21);
            mmabf(S[0][3], q00, q01, q02, q03, b30, b31);
            mmabf(S[1][0], q10, q11, q12, q13, b00, b01);
            mmabf(S[1][1], q10, q11, q12, q13, b10, b11);
            mmabf(S[1][2], q10, q11, q12, q13, b20, b21);
            mmabf(S[1][3], q10, q11, q12, q13, b30, b31);
        }

        // ---- P = exp2(S - SHIFT); L partials stay in registers ----
#pragma unroll
        for (int f = 0; f < 2; ++f) {
            int r0 = 32 * wr + 16 * f + gq;
            float s0 = 0.0f, s1 = 0.0f;
#pragma unroll
            for (int t = 0; t < 4; ++t) {
                S[f][t].x = ex2f(S[f][t].x - SHIFT);
                S[f][t].y = ex2f(S[f][t].y - SHIFT);
                S[f][t].z = ex2f(S[f][t].z - SHIFT);
                S[f][t].w = ex2f(S[f][t].w - SHIFT);
                s0 += S[f][t].x + S[f][t].y;
                s1 += S[f][t].z + S[f][t].w;
                int col = 32 * wc + 8 * t + 2 * qd;
                *(u32*)(smh + OFF_P + r0 * P_S + col) = pkbf(S[f][t].x, S[f][t].y);
                *(u32*)(smh + OFF_P + (r0 + 8) * P_S + col) = pkbf(S[f][t].z, S[f][t].w);
            }
            Lp[2 * f] += s0;
            Lp[2 * f + 1] += s1;
        }
        __syncthreads();   // (C) P visible

        // ---- O += P V ----
#pragma unroll
        for (int kk = 0; kk < 4; ++kk) {
            u32 pa[4][4];
#pragma unroll
            for (int rf = 0; rf < 4; ++rf)
                ldmx4(pa[rf][0], pa[rf][1], pa[rf][2], pa[rf][3],
                      aPb + rf * (16 * P_S * 2) + kk * 32);
            u32 vrow = vbuf + aVoff + kk * (16 * V_S * 2);
#pragma unroll
            for (int p = 0; p < 4; ++p) {
                u32 b0, b1, b2, b3;
                ldmx4t(b0, b1, b2, b3, vrow + p * 32);
#pragma unroll
                for (int rf = 0; rf < 4; ++rf) {
                    mmabf(acc[rf][2 * p], pa[rf][0], pa[rf][1], pa[rf][2], pa[rf][3], b0, b1);
                    mmabf(acc[rf][2 * p + 1], pa[rf][0], pa[rf][1], pa[rf][2], pa[rf][3], b2, b3);
                }
            }
        }
        __syncthreads();   // (D) consumers done

        if (more) {
            const __nv_bfloat16* Kg = Kg0 + (size_t)(tl + 2) * 64 * DI;
            const __nv_bfloat16* Vg = Vg0 + (size_t)(tl + 2) * 64 * DV;
            u32 kd = smbase + (OFF_K + (tl & 1) * 8704) * 2;
            u32 vd = smbase + (OFF_V + (tl & 1) * 16896) * 2;
#pragma unroll
            for (int it = 0; it < 4; ++it) {
                int r = rQ + 16 * it;
                cp16(kd + (r * QK_S + cQ) * 2, Kg + (size_t)r * DI + cQ);
            }
#pragma unroll
            for (int it = 0; it < 8; ++it) {
                int r = rV + 8 * it;
                cp16(vd + (r * V_S + cV) * 2, Vg + (size_t)r * DV + cV);
            }
            CP_COMMIT();
        }
    }

    // ---- epilogue: reduce L once, write corr = acc / L (bf16) ----
#pragma unroll
    for (int f = 0; f < 2; ++f) {
        float s0 = Lp[2 * f], s1 = Lp[2 * f + 1];
        s0 += __shfl_xor_sync(0xffffffffu, s0, 1);
        s0 += __shfl_xor_sync(0xffffffffu, s0, 2);
        s1 += __shfl_xor_sync(0xffffffffu, s1, 1);
        s1 += __shfl_xor_sync(0xffffffffu, s1, 2);
        if (qd == 0) {
            int r0 = 32 * wr + 16 * f + gq;
            red[wc * 128 + r0] = s0;
            red[wc * 128 + r0 + 8] = s1;
        }
    }
    __syncthreads();
    __nv_bfloat16* og = g_corrh + ((size_t)b * NTOK + nbase) * DV;
#pragma unroll
    for (int rf = 0; rf < 4; ++rf) {
        int ra = 64 * wp + 16 * rf + gq;
        float ia = 1.0f / (red[ra] + red[128 + ra]);
        float ib = 1.0f / (red[ra + 8] + red[128 + ra + 8]);
#pragma unroll
        for (int t = 0; t < 8; ++t) {
            int col = 64 * wq + 8 * t + 2 * qd;
            *(u32*)&og[(size_t)ra * DV + col] = pkbf(acc[rf][t].x * ia, acc[rf][t].y * ia);
            *(u32*)&og[(size_t)(ra + 8) * DV + col] = pkbf(acc[rf][t].z * ib, acc[rf][t].w * ib);
        }
    }
}

// ============================================================================
// Output projection (unchanged from round 8)
// ============================================================================
#define PF_OFFW 16896
#define SMEM_PF ((16896 + 33792) * 2)

__global__ __launch_bounds__(256, 2)
void projf_tc_kernel(const float* __restrict__ sp, const float* __restrict__ tp,
                     float* __restrict__ out) {
    extern __shared__ uint16_t psm[];
    const int b = blockIdx.z, obase = blockIdx.y * 128, nbase = blockIdx.x * 64;
    const int tid = threadIdx.x, lane = tid & 31, wid = tid >> 5;
    const int gq = lane >> 2, qd = lane & 3;
    const u32 smbase = smaddr(psm);

    {
        const __nv_bfloat16* cg = g_corrh + ((size_t)b * NTOK + nbase) * DV;
        int seg = (tid & 31) * 8;
#pragma unroll
        for (int it = 0; it < 8; ++it) {
            int r = (tid >> 5) + 8 * it;
            cp16(smbase + (r * WS_S + seg) * 2, cg + (size_t)r * DV + seg);
        }
        const __nv_bfloat16* wg = g_Wph + (size_t)obase * 256;
#pragma unroll
        for (int it = 0; it < 16; ++it) {
            int r = (tid >> 5) + 8 * it;
            cp16(smbase + (PF_OFFW + r * WS_S + seg) * 2, wg + (size_t)r * 256 + seg);
        }
    }
    CP_COMMIT(); CP_WAIT0();
    __syncthreads();

    const u32 aA = smbase + (PF_OFFW + (16 * wid + (lane & 15)) * WS_S + (lane >> 4) * 8) * 2;
    const u32 aB = smbase + (((lane & 7) + ((lane >> 4) & 1) * 8) * WS_S +
                             ((lane >> 3) & 1) * 8) * 2;

    float4 acc[8];
#pragma unroll
    for (int t = 0; t < 8; ++t) acc[t] = make_float4(0.f, 0.f, 0.f, 0.f);

#pragma unroll
    for (int kk = 0; kk < 16; ++kk) {
        u32 a0, a1, a2, a3;
        ldmx4(a0, a1, a2, a3, aA + kk * 16 * 2);
#pragma unroll
        for (int j = 0; j < 4; ++j) {
            u32 b0, b1, b2, b3;
            ldmx4(b0, b1, b2, b3, aB + (j * 16 * WS_S + kk * 16) * 2);
            mmabf(acc[2 * j], a0, a1, a2, a3, b0, b1);
            mmabf(acc[2 * j + 1], a0, a1, a2, a3, b2, b3);
        }
    }

    const int o0 = obase + 16 * wid + gq;
    float bs0 = g_base[b * OUTC + o0], bs1 = g_base[b * OUTC + o0 + 8];
    float sp0 = sp[o0], sp1 = sp[o0 + 8], tp0 = tp[o0], tp1 = tp[o0 + 8];
    float* og0 = out + ((size_t)b * OUTC + o0) * NTOK + nbase;
    float* og1 = og0 + (size_t)8 * NTOK;
#pragma unroll
    for (int t = 0; t < 8; ++t) {
        int n = 8 * t + 2 * qd;
        float2 r0, r1;
        r0.x = fmaxf((bs0 - acc[t].x) * sp0 + tp0, 0.f);
        r0.y = fmaxf((bs0 - acc[t].y) * sp0 + tp0, 0.f);
        r1.x = fmaxf((bs1 - acc[t].z) * sp1 + tp1, 0.f);
        r1.y = fmaxf((bs1 - acc[t].w) * sp1 + tp1, 0.f);
        *(float2*)&og0[n] = r0;
        *(float2*)&og1[n] = r1;
    }
}

extern "C" void kernel_launch(void* const* d_in, const int* in_sizes, int n_in,
                              void* d_out, int out_size) {
    const float* x1 = (const float*)d_in[0];
    const float* x2 = (const float*)d_in[1];
    const float* Wq = (const float*)d_in[2];
    const float* bq = (const float*)d_in[3];
    const float* sq = (const float*)d_in[4];
    const float* tq = (const float*)d_in[5];
    const float* Wk = (const float*)d_in[6];
    const float* bk = (const float*)d_in[7];
    const float* sk = (const float*)d_in[8];
    const float* tk = (const float*)d_in[9];
    const float* Wv = (const float*)d_in[10];
    const float* bv = (const float*)d_in[11];
    const float* sv = (const float*)d_in[12];
    const float* tv = (const float*)d_in[13];
    const float* Wp = (const float*)d_in[14];
    const float* bp = (const float*)d_in[15];
    const float* sp = (const float*)d_in[16];
    const float* tp = (const float*)d_in[17];
    float* out = (float*)d_out;

    cudaFuncSetAttribute(qkv_tc_kernel, cudaFuncAttributeMaxDynamicSharedMemorySize, SMEM_QKV);
    cudaFuncSetAttribute(attn_kernel, cudaFuncAttributeMaxDynamicSharedMemorySize, SMEM_ATTN);
    cudaFuncSetAttribute(projf_tc_kernel, cudaFuncAttributeMaxDynamicSharedMemorySize, SMEM_PF);

    cvt_x_kernel<<<dim3(4096, 2), 256>>>(x1, x2);
    cvt_w_kernel<<<dim3(64, 4), 256>>>(Wq, Wk, Wv, Wp);
    zero_csum_kernel<<<1, BATCH * DV>>>();
    qkv_tc_kernel<<<dim3(NTOK / 64, BATCH, 4), 256, SMEM_QKV>>>(
        bq, sq, tq, bk, sk, tk, bv, sv, tv);
    base_kernel<<<BATCH, 256>>>(Wp, bp);
    attn_kernel<<<dim3(NTOK / 128, BATCH), 256, SMEM_ATTN>>>();
    projf_tc_kernel<<<dim3(NTOK / 64, OUTC / 128, BATCH), 256, SMEM_PF>>>(sp, tp, out);
}

// round 12
// speedup vs baseline: 3.0777x; 1.0142x over previous
#include <cuda_runtime.h>
#include <cuda_bf16.h>
#include <cstdint>

#define NTOK 4096
#define BATCH 4
#define CIN 256
#define DI 128
#define DV 256
#define OUTC 256

typedef unsigned long long u64;
typedef uint32_t u32;

// ---------------- bf16 mma + ldmatrix ----------------
__device__ __forceinline__ void mmabf(float4& d, u32 a0, u32 a1, u32 a2, u32 a3,
                                      u32 b0, u32 b1) {
    asm volatile(
        "mma.sync.aligned.m16n8k16.row.col.f32.bf16.bf16.f32 "
        "{%0,%1,%2,%3}, {%4,%5,%6,%7}, {%8,%9}, {%0,%1,%2,%3};"
        : "+f"(d.x), "+f"(d.y), "+f"(d.z), "+f"(d.w)
        : "r"(a0), "r"(a1), "r"(a2), "r"(a3), "r"(b0), "r"(b1));
}
__device__ __forceinline__ void ldmx4(u32& r0, u32& r1, u32& r2, u32& r3, u32 a) {
    asm volatile("ldmatrix.sync.aligned.m8n8.x4.shared.b16 {%0,%1,%2,%3}, [%4];"
                 : "=r"(r0), "=r"(r1), "=r"(r2), "=r"(r3) : "r"(a));
}
__device__ __forceinline__ void ldmx4t(u32& r0, u32& r1, u32& r2, u32& r3, u32 a) {
    asm volatile("ldmatrix.sync.aligned.m8n8.x4.trans.shared.b16 {%0,%1,%2,%3}, [%4];"
                 : "=r"(r0), "=r"(r1), "=r"(r2), "=r"(r3) : "r"(a));
}
__device__ __forceinline__ u32 pkbf(float lo, float hi) {
    u32 r; asm("cvt.rn.bf16x2.f32 %0, %1, %2;" : "=r"(r) : "f"(hi), "f"(lo)); return r;
}
__device__ __forceinline__ float ex2f(float x) {
    float r; asm("ex2.approx.f32 %0, %1;" : "=f"(r) : "f"(x)); return r;
}

// ---------------- cp.async helpers ----------------
__device__ __forceinline__ u32 smaddr(const void* p) {
    return (u32)__cvta_generic_to_shared(p);
}
__device__ __forceinline__ void cp16(u32 dst, const void* src) {
    asm volatile("cp.async.cg.shared.global [%0], [%1], 16;" :: "r"(dst), "l"(src));
}
#define CP_COMMIT() asm volatile("cp.async.commit_group;")
#define CP_WAIT1()  asm volatile("cp.async.wait_group 1;")
#define CP_WAIT0()  asm volatile("cp.async.wait_group 0;")

// ---------------- scratch ----------------
__device__ __nv_bfloat16 g_x1h[BATCH * CIN * NTOK];
__device__ __nv_bfloat16 g_x2h[BATCH * CIN * NTOK];
__device__ __nv_bfloat16 g_Wh[3 * 128 * 256];
__device__ __nv_bfloat16 g_Wph[256 * 256];
__device__ __nv_bfloat16 g_Qh[BATCH * NTOK * DI];    // pre-scaled by 128^-0.5 * log2(e)
__device__ __nv_bfloat16 g_Kh[BATCH * NTOK * DI];
__device__ __nv_bfloat16 g_Vh[BATCH * NTOK * DV];    // [0:128)=v2, [128:256)=v1
__device__ __nv_bfloat16 g_corrh[BATCH * NTOK * DV]; // P·V/L (bf16)
__device__ float g_csum[BATCH * DV];
__device__ float g_base[BATCH * OUTC];

// ---------------- tiny kernels ----------------
__global__ void zero_csum_kernel() { g_csum[threadIdx.x] = 0.0f; }

__global__ void cvt_x_kernel(const float* __restrict__ x1, const float* __restrict__ x2) {
    const float* src = blockIdx.y ? x2 : x1;
    __nv_bfloat16* dst = blockIdx.y ? g_x2h : g_x1h;
    int idx = (blockIdx.x * 256 + threadIdx.x) * 4;
    float4 v = *(const float4*)&src[idx];
    *(uint2*)&dst[idx] = make_uint2(pkbf(v.x, v.y), pkbf(v.z, v.w));
}

__global__ void cvt_w_kernel(const float* __restrict__ Wq, const float* __restrict__ Wk,
                             const float* __restrict__ Wv, const float* __restrict__ Wp) {
    int y = blockIdx.y;
    const float* src = (y == 0) ? Wq : (y == 1) ? Wk : (y == 2) ? Wv : Wp;
    __nv_bfloat16* dst = (y < 3) ? (g_Wh + y * 32768) : g_Wph;
    int n = (y < 3) ? 32768 : 65536;
    int idx = (blockIdx.x * 256 + threadIdx.x) * 4;
    if (idx < n) {
        float4 v = *(const float4*)&src[idx];
        *(uint2*)&dst[idx] = make_uint2(pkbf(v.x, v.y), pkbf(v.z, v.w));
    }
}

__global__ void base_kernel(const float* __restrict__ Wp, const float* __restrict__ bp) {
    __shared__ float cs[256];
    int b = blockIdx.x, o = threadIdx.x;
    cs[o] = g_csum[b * DV + o];
    __syncthreads();
    float s = bp[o];
    const float* w = Wp + (size_t)o * 256;
#pragma unroll 8
    for (int c = 0; c < 256; ++c) s += w[c] * cs[c];
    g_base[b * OUTC + o] = s;
}

// ============================================================================
// QKV projection (unchanged from round 11)
// ============================================================================
#define XS_S 72
#define WS_S 264
#define QK_OFFW 18432
#define QK_OFFC 52224
#define SMEM_QKV (52224 * 2 + 512)

__global__ __launch_bounds__(256, 2)
void qkv_tc_kernel(const float* __restrict__ bq, const float* __restrict__ sq,
                   const float* __restrict__ tq,
                   const float* __restrict__ bk, const float* __restrict__ sk,
                   const float* __restrict__ tk,
                   const float* __restrict__ bv, const float* __restrict__ sv,
                   const float* __restrict__ tv) {
    extern __shared__ uint16_t qsm[];
    float* colacc = (float*)(qsm + QK_OFFC);
    const int z = blockIdx.z, b = blockIdx.y, nbase = blockIdx.x * 64;
    const int tid = threadIdx.x, lane = tid & 31, wid = tid >> 5;
    const int wn = wid & 3, wo = wid >> 2;
    const int gq = lane >> 2, qd = lane & 3;
    const __nv_bfloat16* xh = (z == 0 || z == 3) ? g_x1h : g_x2h;
    const __nv_bfloat16* wg = g_Wh + (z < 2 ? z : 2) * 32768;
    const float* bias = (z == 0) ? bq : (z == 1) ? bk : bv;
    const float* sc = (z == 0) ? sq : (z == 1) ? sk : sv;
    const float* tr = (z == 0) ? tq : (z == 1) ? tk : tv;
    const float prescale = (z == 0) ? 0.12751743f : 1.0f;
    const u32 smbase = smaddr(qsm);

    if (tid < 128) colacc[tid] = 0.0f;

    const __nv_bfloat16* xg = xh + (size_t)b * CIN * NTOK + nbase;
    const int segX = (tid & 7) * 8;
    const int segW = (tid & 15) * 8;
#pragma unroll
    for (int it = 0; it < 4; ++it) {
        int r = (tid >> 3) + 32 * it;
        cp16(smbase + (r * XS_S + segX) * 2, xg + (size_t)r * NTOK + segX);
    }
#pragma unroll
    for (int it = 0; it < 8; ++it) {
        int r = (tid >> 4) + 16 * it;
        cp16(smbase + (QK_OFFW + r * WS_S + segW) * 2, wg + (size_t)r * 256 + segW);
    }
    CP_COMMIT();
#pragma unroll
    for (int it = 4; it < 8; ++it) {
        int r = (tid >> 3) + 32 * it;
        cp16(smbase + (r * XS_S + segX) * 2, xg + (size_t)r * NTOK + segX);
    }
#pragma unroll
    for (int it = 0; it < 8; ++it) {
        int r = (tid >> 4) + 16 * it;
        cp16(smbase + (QK_OFFW + r * WS_S + segW + 128) * 2, wg + (size_t)r * 256 + segW + 128);
    }
    CP_COMMIT();

    const u32 aX = smbase + ((((lane & 7) + ((lane >> 4) & 1) * 8)) * XS_S +
                             16 * wn + ((lane >> 3) & 1) * 8) * 2;
    const u32 aW = smbase + (QK_OFFW + (64 * wo + (lane & 7) + ((lane >> 4) & 1) * 8) * WS_S +
                             ((lane >> 3) & 1) * 8) * 2;

    float4 acc[8];
#pragma unroll
    for (int t = 0; t < 8; ++t) acc[t] = make_float4(0.f, 0.f, 0.f, 0.f);

    CP_WAIT1();
    __syncthreads();
#pragma unroll
    for (int kk = 0; kk < 8; ++kk) {
        u32 a0, a1, a2, a3;
        ldmx4t(a0, a1, a2, a3, aX + kk * 16 * XS_S * 2);
#pragma unroll
        for (int j = 0; j < 4; ++j) {
            u32 b0, b1, b2, b3;
            ldmx4(b0, b1, b2, b3, aW + (j * 16 * WS_S + kk * 16) * 2);
            mmabf(acc[2 * j], a0, a1, a2, a3, b0, b1);
            mmabf(acc[2 * j + 1], a0, a1, a2, a3, b2, b3);
        }
    }
    CP_WAIT0();
    __syncthreads();
#pragma unroll
    for (int kk = 8; kk < 16; ++kk) {
        u32 a0, a1, a2, a3;
        ldmx4t(a0, a1, a2, a3, aX + kk * 16 * XS_S * 2);
#pragma unroll
        for (int j = 0; j < 4; ++j) {
            u32 b0, b1, b2, b3;
            ldmx4(b0, b1, b2, b3, aW + (j * 16 * WS_S + kk * 16) * 2);
            mmabf(acc[2 * j], a0, a1, a2, a3, b0, b1);
            mmabf(acc[2 * j + 1], a0, a1, a2, a3, b2, b3);
        }
    }

    const int n0 = 16 * wn + gq;
    const size_t rg = (size_t)b * NTOK + nbase + n0;
#pragma unroll
    for (int t = 0; t < 8; ++t) {
        int o = 64 * wo + 8 * t + 2 * qd;
        float2 bb = *(const float2*)&bias[o];
        float2 ss = *(const float2*)&sc[o];
        float2 tt = *(const float2*)&tr[o];
        float v00 = fmaxf((acc[t].x + bb.x) * ss.x + tt.x, 0.f) * prescale;
        float v01 = fmaxf((acc[t].y + bb.y) * ss.y + tt.y, 0.f) * prescale;
        float v10 = fmaxf((acc[t].z + bb.x) * ss.x + tt.x, 0.f) * prescale;
        float v11 = fmaxf((acc[t].w + bb.y) * ss.y + tt.y, 0.f) * prescale;
        if (z == 0) {
            *(u32*)&g_Qh[rg * DI + o] = pkbf(v00, v01);
            *(u32*)&g_Qh[(rg + 8) * DI + o] = pkbf(v10, v11);
        } else if (z == 1) {
            *(u32*)&g_Kh[rg * DI + o] = pkbf(v00, v01);
            *(u32*)&g_Kh[(rg + 8) * DI + o] = pkbf(v10, v11);
        } else {
            int oc = o + (z == 3 ? 128 : 0);
            *(u32*)&g_Vh[rg * DV + oc] = pkbf(v00, v01);
            *(u32*)&g_Vh[(rg + 8) * DV + oc] = pkbf(v10, v11);
            atomicAdd(&colacc[o], v00 + v10);
            atomicAdd(&colacc[o + 1], v01 + v11);
        }
    }
    if (z >= 2) {
        __syncthreads();
        if (tid < 128) {
            int ofs = (z == 3) ? 128 : 0;
            atomicAdd(&g_csum[b * DV + ofs + tid], colacc[tid]);
        }
    }
}

// ============================================================================
// bf16 flash attention, NO-MAX softmax, BR=128, BC=128 supertiles (32 iters).
// S: 4(row x32) x 2(col x64, two 32-wide register halves); PV: 2(row x64) x 4(col x64).
// K single-buffered (prefetch overlaps PV); V single-buffered (prefetch overlaps S).
// 4 syncs per 128 tokens (was 6).
// ============================================================================
#define QK_S 136
#define V_S  264
#define P_S  136
#define OFF_K 17408
#define OFF_V 34816
#define OFF_P 68608
#define OFF_RED 86016
#define SMEM_ATTN (OFF_RED * 2 + 256 * 4)
#define SHIFT 8.0f

__global__ __launch_bounds__(256, 1)
void attn_kernel() {
    extern __shared__ uint16_t smh[];
    float* red = (float*)(smh + OFF_RED);   // 256 floats: L partials (2 col groups x 128 rows)

    const int b = blockIdx.y;
    const int nbase = blockIdx.x * 128;
    const int tid = threadIdx.x;
    const int wid = tid >> 5, lane = tid & 31;
    const int wr = wid >> 1, wc = wid & 1;
    const int wp = wid >> 2, wq = wid & 3;
    const int gq = lane >> 2, qd = lane & 3;

    const int rQ = tid >> 4, cQ = (tid & 15) * 8;
    const int rV = tid >> 5, cV = (tid & 31) * 8;
    const __nv_bfloat16* Qg = g_Qh + ((size_t)b * NTOK + nbase) * DI;
    const __nv_bfloat16* Kg0 = g_Kh + (size_t)b * NTOK * DI;
    const __nv_bfloat16* Vg0 = g_Vh + (size_t)b * NTOK * DV;
    const u32 smbase = smaddr(smh);

    // prologue: group0 = {Q, K(0)}, group1 = {V(0)}
#pragma unroll
    for (int it = 0; it < 8; ++it) {
        int r = rQ + 16 * it;
        cp16(smbase + (r * QK_S + cQ) * 2, Qg + (size_t)r * DI + cQ);
        cp16(smbase + (OFF_K + r * QK_S + cQ) * 2, Kg0 + (size_t)r * DI + cQ);
    }
    CP_COMMIT();
#pragma unroll
    for (int it = 0; it < 16; ++it) {
        int r = rV + 8 * it;
        cp16(smbase + (OFF_V + r * V_S + cV) * 2, Vg0 + (size_t)r * DV + cV);
    }
    CP_COMMIT();

    const u32 aQ0 = smbase + ((32 * wr + (lane & 15)) * QK_S + (lane >> 4) * 8) * 2;
    const u32 aQ1 = aQ0 + 16 * QK_S * 2;
    const u32 aKbase = smbase + OFF_K * 2 +
        ((64 * wc + (lane & 7) + ((lane >> 4) & 1) * 8) * QK_S + ((lane >> 3) & 1) * 8) * 2;
    const u32 aPb = smbase + (OFF_P + (64 * wp + (lane & 15)) * P_S + (lane >> 4) * 8) * 2;
    const u32 aVb = smbase + OFF_V * 2 +
        (((lane & 7) + ((lane >> 3) & 1) * 8) * V_S + 64 * wq + (lane >> 4) * 8) * 2;

    float Lp[4] = {0.f, 0.f, 0.f, 0.f};   // [2f+h]: row 32wr+16f+gq+8h
    float4 acc[4][8];
#pragma unroll
    for (int rf = 0; rf < 4; ++rf)
#pragma unroll
        for (int t = 0; t < 8; ++t) acc[rf][t] = make_float4(0.f, 0.f, 0.f, 0.f);

    for (int tl = 0; tl < 32; ++tl) {
        const bool more = (tl + 1) < 32;
        CP_WAIT1();           // K(tl) (and Q) done; V(tl) may fly
        __syncthreads();      // (A)

        // ---- S = Q K^T, exp2(S-SHIFT) -> P, in two 32-col halves ----
#pragma unroll
        for (int ch = 0; ch < 2; ++ch) {
            float4 S[2][4];
#pragma unroll
            for (int f = 0; f < 2; ++f)
#pragma unroll
                for (int t = 0; t < 4; ++t) S[f][t] = make_float4(0.f, 0.f, 0.f, 0.f);
            const u32 aK = aKbase + ch * (32 * QK_S * 2);
            const u32 aK2 = aK + 16 * QK_S * 2;
#pragma unroll
            for (int kk = 0; kk < 8; ++kk) {
                u32 q00, q01, q02, q03, q10, q11, q12, q13;
                ldmx4(q00, q01, q02, q03, aQ0 + kk * 32);
                ldmx4(q10, q11, q12, q13, aQ1 + kk * 32);
                u32 b00, b01, b10, b11, b20, b21, b30, b31;
                ldmx4(b00, b01, b10, b11, aK + kk * 32);
                ldmx4(b20, b21, b30, b31, aK2 + kk * 32);
                mmabf(S[0][0], q00, q01, q02, q03, b00, b01);
                mmabf(S[0][1], q00, q01, q02, q03, b10, b11);
                mmabf(S[0][2], q00, q01, q02, q03, b20, b21);
                mmabf(S[0][3], q00, q01, q02, q03, b30, b31);
                mmabf(S[1][0], q10, q11, q12, q13, b00, b01);
                mmabf(S[1][1], q10, q11, q12, q13, b10, b11);
                mmabf(S[1][2], q10, q11, q12, q13, b20, b21);
                mmabf(S[1][3], q10, q11, q12, q13, b30, b31);
            }
#pragma unroll
            for (int f = 0; f < 2; ++f) {
                int r0 = 32 * wr + 16 * f + gq;
                float s0 = 0.0f, s1 = 0.0f;
#pragma unroll
                for (int t = 0; t < 4; ++t) {
                    S[f][t].x = ex2f(S[f][t].x - SHIFT);
                    S[f][t].y = ex2f(S[f][t].y - SHIFT);
                    S[f][t].z = ex2f(S[f][t].z - SHIFT);
                    S[f][t].w = ex2f(S[f][t].w - SHIFT);
                    s0 += S[f][t].x + S[f][t].y;
                    s1 += S[f][t].z + S[f][t].w;
                    int col = 64 * wc + 32 * ch + 8 * t + 2 * qd;
                    *(u32*)(smh + OFF_P + r0 * P_S + col) = pkbf(S[f][t].x, S[f][t].y);
                    *(u32*)(smh + OFF_P + (r0 + 8) * P_S + col) = pkbf(S[f][t].z, S[f][t].w);
                }
                Lp[2 * f] += s0;
                Lp[2 * f + 1] += s1;
            }
        }
        __syncthreads();      // (B) K reads done, P visible

        // prefetch K(tl+1) into same buffer (overlaps PV)
        if (more) {
            const __nv_bfloat16* Kg = Kg0 + (size_t)(tl + 1) * 128 * DI;
#pragma unroll
            for (int it = 0; it < 8; ++it) {
                int r = rQ + 16 * it;
                cp16(smbase + (OFF_K + r * QK_S + cQ) * 2, Kg + (size_t)r * DI + cQ);
            }
            CP_COMMIT();
        }
        if (more) CP_WAIT1(); else CP_WAIT0();   // V(tl) done; K(tl+1) may fly
        __syncthreads();      // (C) V visible

        // ---- O += P V : k=128 ----
#pragma unroll
        for (int kk = 0; kk < 8; ++kk) {
            u32 pa[4][4];
#pragma unroll
            for (int rf = 0; rf < 4; ++rf)
                ldmx4(pa[rf][0], pa[rf][1], pa[rf][2], pa[rf][3],
                      aPb + rf * (16 * P_S * 2) + kk * 32);
            u32 vrow = aVb + kk * (16 * V_S * 2);
#pragma unroll
            for (int p = 0; p < 4; ++p) {
                u32 b0, b1, b2, b3;
                ldmx4t(b0, b1, b2, b3, vrow + p * 32);
#pragma unroll
                for (int rf = 0; rf < 4; ++rf) {
                    mmabf(acc[rf][2 * p], pa[rf][0], pa[rf][1], pa[rf][2], pa[rf][3], b0, b1);
                    mmabf(acc[rf][2 * p + 1], pa[rf][0], pa[rf][1], pa[rf][2], pa[rf][3], b2, b3);
                }
            }
        }
        __syncthreads();      // (D) V/P consumers done

        // prefetch V(tl+1) into same buffer (overlaps next S)
        if (more) {
            const __nv_bfloat16* Vg = Vg0 + (size_t)(tl + 1) * 128 * DV;
#pragma unroll
            for (int it = 0; it < 16; ++it) {
                int r = rV + 8 * it;
                cp16(smbase + (OFF_V + r * V_S + cV) * 2, Vg + (size_t)r * DV + cV);
            }
            CP_COMMIT();
        }
    }

    // ---- epilogue: reduce L once, write corr = acc / L (bf16) ----
#pragma unroll
    for (int f = 0; f < 2; ++f) {
        float s0 = Lp[2 * f], s1 = Lp[2 * f + 1];
        s0 += __shfl_xor_sync(0xffffffffu, s0, 1);
        s0 += __shfl_xor_sync(0xffffffffu, s0, 2);
        s1 += __shfl_xor_sync(0xffffffffu, s1, 1);
        s1 += __shfl_xor_sync(0xffffffffu, s1, 2);
        if (qd == 0) {
            int r0 = 32 * wr + 16 * f + gq;
            red[wc * 128 + r0] = s0;
            red[wc * 128 + r0 + 8] = s1;
        }
    }
    __syncthreads();
    __nv_bfloat16* og = g_corrh + ((size_t)b * NTOK + nbase) * DV;
#pragma unroll
    for (int rf = 0; rf < 4; ++rf) {
        int ra = 64 * wp + 16 * rf + gq;
        float ia = 1.0f / (red[ra] + red[128 + ra]);
        float ib = 1.0f / (red[ra + 8] + red[128 + ra + 8]);
#pragma unroll
        for (int t = 0; t < 8; ++t) {
            int col = 64 * wq + 8 * t + 2 * qd;
            *(u32*)&og[(size_t)ra * DV + col] = pkbf(acc[rf][t].x * ia, acc[rf][t].y * ia);
            *(u32*)&og[(size_t)(ra + 8) * DV + col] = pkbf(acc[rf][t].z * ib, acc[rf][t].w * ib);
        }
    }
}

// ============================================================================
// Output projection (unchanged from round 11)
// ============================================================================
#define PF_OFFW 16896
#define SMEM_PF ((16896 + 33792) * 2)

__global__ __launch_bounds__(256, 2)
void projf_tc_kernel(const float* __restrict__ sp, const float* __restrict__ tp,
                     float* __restrict__ out) {
    extern __shared__ uint16_t psm[];
    const int b = blockIdx.z, obase = blockIdx.y * 128, nbase = blockIdx.x * 64;
    const int tid = threadIdx.x, lane = tid & 31, wid = tid >> 5;
    const int gq = lane >> 2, qd = lane & 3;
    const u32 smbase = smaddr(psm);

    {
        const __nv_bfloat16* cg = g_corrh + ((size_t)b * NTOK + nbase) * DV;
        int seg = (tid & 31) * 8;
#pragma unroll
        for (int it = 0; it < 8; ++it) {
            int r = (tid >> 5) + 8 * it;
            cp16(smbase + (r * WS_S + seg) * 2, cg + (size_t)r * DV + seg);
        }
        const __nv_bfloat16* wg = g_Wph + (size_t)obase * 256;
#pragma unroll
        for (int it = 0; it < 16; ++it) {
            int r = (tid >> 5) + 8 * it;
            cp16(smbase + (PF_OFFW + r * WS_S + seg) * 2, wg + (size_t)r * 256 + seg);
        }
    }
    CP_COMMIT(); CP_WAIT0();
    __syncthreads();

    const u32 aA = smbase + (PF_OFFW + (16 * wid + (lane & 15)) * WS_S + (lane >> 4) * 8) * 2;
    const u32 aB = smbase + (((lane & 7) + ((lane >> 4) & 1) * 8) * WS_S +
                             ((lane >> 3) & 1) * 8) * 2;

    float4 acc[8];
#pragma unroll
    for (int t = 0; t < 8; ++t) acc[t] = make_float4(0.f, 0.f, 0.f, 0.f);

#pragma unroll
    for (int kk = 0; kk < 16; ++kk) {
        u32 a0, a1, a2, a3;
        ldmx4(a0, a1, a2, a3, aA + kk * 16 * 2);
#pragma unroll
        for (int j = 0; j < 4; ++j) {
            u32 b0, b1, b2, b3;
            ldmx4(b0, b1, b2, b3, aB + (j * 16 * WS_S + kk * 16) * 2);
            mmabf(acc[2 * j], a0, a1, a2, a3, b0, b1);
            mmabf(acc[2 * j + 1], a0, a1, a2, a3, b2, b3);
        }
    }

    const int o0 = obase + 16 * wid + gq;
    float bs0 = g_base[b * OUTC + o0], bs1 = g_base[b * OUTC + o0 + 8];
    float sp0 = sp[o0], sp1 = sp[o0 + 8], tp0 = tp[o0], tp1 = tp[o0 + 8];
    float* og0 = out + ((size_t)b * OUTC + o0) * NTOK + nbase;
    float* og1 = og0 + (size_t)8 * NTOK;
#pragma unroll
    for (int t = 0; t < 8; ++t) {
        int n = 8 * t + 2 * qd;
        float2 r0, r1;
        r0.x = fmaxf((bs0 - acc[t].x) * sp0 + tp0, 0.f);
        r0.y = fmaxf((bs0 - acc[t].y) * sp0 + tp0, 0.f);
        r1.x = fmaxf((bs1 - acc[t].z) * sp1 + tp1, 0.f);
        r1.y = fmaxf((bs1 - acc[t].w) * sp1 + tp1, 0.f);
        *(float2*)&og0[n] = r0;
        *(float2*)&og1[n] = r1;
    }
}

extern "C" void kernel_launch(void* const* d_in, const int* in_sizes, int n_in,
                              void* d_out, int out_size) {
    const float* x1 = (const float*)d_in[0];
    const float* x2 = (const float*)d_in[1];
    const float* Wq = (const float*)d_in[2];
    const float* bq = (const float*)d_in[3];
    const float* sq = (const float*)d_in[4];
    const float* tq = (const float*)d_in[5];
    const float* Wk = (const float*)d_in[6];
    const float* bk = (const float*)d_in[7];
    const float* sk = (const float*)d_in[8];
    const float* tk = (const float*)d_in[9];
    const float* Wv = (const float*)d_in[10];
    const float* bv = (const float*)d_in[11];
    const float* sv = (const float*)d_in[12];
    const float* tv = (const float*)d_in[13];
    const float* Wp = (const float*)d_in[14];
    const float* bp = (const float*)d_in[15];
    const float* sp = (const float*)d_in[16];
    const float* tp = (const float*)d_in[17];
    float* out = (float*)d_out;

    cudaFuncSetAttribute(qkv_tc_kernel, cudaFuncAttributeMaxDynamicSharedMemorySize, SMEM_QKV);
    cudaFuncSetAttribute(attn_kernel, cudaFuncAttributeMaxDynamicSharedMemorySize, SMEM_ATTN);
    cudaFuncSetAttribute(projf_tc_kernel, cudaFuncAttributeMaxDynamicSharedMemorySize, SMEM_PF);

    cvt_x_kernel<<<dim3(4096, 2), 256>>>(x1, x2);
    cvt_w_kernel<<<dim3(64, 4), 256>>>(Wq, Wk, Wv, Wp);
    zero_csum_kernel<<<1, BATCH * DV>>>();
    qkv_tc_kernel<<<dim3(NTOK / 64, BATCH, 4), 256, SMEM_QKV>>>(
        bq, sq, tq, bk, sk, tk, bv, sv, tv);
    base_kernel<<<BATCH, 256>>>(Wp, bp);
    attn_kernel<<<dim3(NTOK / 128, BATCH), 256, SMEM_ATTN>>>();
    projf_tc_kernel<<<dim3(NTOK / 64, OUTC / 128, BATCH), 256, SMEM_PF>>>(sp, tp, out);
}